// round 12
// baseline (speedup 1.0000x reference)
#include <cuda_runtime.h>
#include <cuda_bf16.h>
#include <cstdint>

#define B_ 32
#define L_ 1024
#define D_ 1024
typedef __nv_bfloat16 bf16;

// ---------------------------------------------------------------------------
// Scratch (device globals; no allocation in kernel_launch)
// ---------------------------------------------------------------------------
__device__ bf16  g_xh  [(size_t)B_ * L_ * D_];  // x hi split, [b, l, d]
__device__ bf16  g_xl  [(size_t)B_ * L_ * D_];  // x lo split
__device__ bf16  g_xtch[(size_t)B_ * L_ * D_];  // compact x^T hi, [b, d, j]
__device__ bf16  g_xtcl[(size_t)B_ * L_ * D_];  // compact x^T lo
__device__ float g_scores[(size_t)B_ * L_ * L_]; // compact cols [b, r, j<cnt]
__device__ bf16  g_ah  [(size_t)B_ * L_ * L_];  // compact alpha hi
__device__ bf16  g_al  [(size_t)B_ * L_ * L_];  // compact alpha lo
__device__ int   g_idx [B_ * L_];               // valid-row indices (pad 0)
__device__ int   g_idx2[B_ * L_];               // invalid-row indices (pad 0)
__device__ int   g_pos [B_ * L_];               // exclusive prefix of mask
__device__ int   g_cnt [B_];

// ---------------------------------------------------------------------------
// PTX helpers (baseline ISA only — harness targets plain sm_103, no tcgen05)
// ---------------------------------------------------------------------------
__device__ __forceinline__ uint32_t smem_u32(const void* p) {
    uint32_t a;
    asm("{ .reg .u64 t; cvta.to.shared.u64 t, %1; cvt.u32.u64 %0, t; }" : "=r"(a) : "l"(p));
    return a;
}
#define CP_COMMIT() asm volatile("cp.async.commit_group;" ::: "memory")
#define CP_WAIT1()  asm volatile("cp.async.wait_group 1;" ::: "memory")
#define CP_WAIT0()  asm volatile("cp.async.wait_group 0;" ::: "memory")

__device__ __forceinline__ void cp16(uint32_t dst, const void* src) {
    asm volatile("cp.async.cg.shared.global [%0], [%1], 16;" :: "r"(dst), "l"(src));
}
__device__ __forceinline__ void ldsm4(uint32_t* r, uint32_t addr) {
    asm volatile("ldmatrix.sync.aligned.m8n8.x4.shared.b16 {%0,%1,%2,%3}, [%4];"
                 : "=r"(r[0]), "=r"(r[1]), "=r"(r[2]), "=r"(r[3]) : "r"(addr));
}
__device__ __forceinline__ void mma16816(float* c, const uint32_t* a, const uint32_t* b) {
    asm volatile(
        "mma.sync.aligned.m16n8k16.row.col.f32.bf16.bf16.f32 "
        "{%0,%1,%2,%3}, {%4,%5,%6,%7}, {%8,%9}, {%0,%1,%2,%3};"
        : "+f"(c[0]), "+f"(c[1]), "+f"(c[2]), "+f"(c[3])
        : "r"(a[0]), "r"(a[1]), "r"(a[2]), "r"(a[3]), "r"(b[0]), "r"(b[1]));
}

// ---------------------------------------------------------------------------
// mask_scan: per batch, exclusive prefix -> g_pos, g_idx (valid), g_idx2
// (invalid), g_cnt.
// ---------------------------------------------------------------------------
__global__ __launch_bounds__(256) void mask_scan(const int* __restrict__ xmask)
{
    const int b = blockIdx.x;
    const int tid = threadIdx.x;
    const int lane = tid & 31, wid = tid >> 5;
    const int4 m = *(const int4*)(xmask + b * L_ + tid * 4);
    const int c[4] = { (m.x != 0), (m.y != 0), (m.z != 0), (m.w != 0) };
    const int tot = c[0] + c[1] + c[2] + c[3];

    int incl = tot;
#pragma unroll
    for (int o = 1; o < 32; o <<= 1) {
        int v = __shfl_up_sync(0xffffffffu, incl, o);
        if (lane >= o) incl += v;
    }
    __shared__ int ws[8];
    if (lane == 31) ws[wid] = incl;
    __syncthreads();
    if (tid < 8) {
        int v = ws[tid];
#pragma unroll
        for (int o = 1; o < 8; o <<= 1) {
            int u = __shfl_up_sync(0xffu, v, o);
            if (tid >= o) v += u;
        }
        ws[tid] = v;
    }
    __syncthreads();
    int base = (wid > 0 ? ws[wid - 1] : 0) + (incl - tot);
    const int cnt = ws[7];
    const int cnt2 = L_ - cnt;

    const int l = tid * 4;
    int p = base;
#pragma unroll
    for (int k = 0; k < 4; k++) {
        const int lg = l + k;
        if (c[k]) { g_idx[b * L_ + p] = lg; p++; }
        else      { g_idx2[b * L_ + (lg - p)] = lg; }
    }
    g_pos[b * L_ + l + 0] = base;
    g_pos[b * L_ + l + 1] = base + c[0];
    g_pos[b * L_ + l + 2] = base + c[0] + c[1];
    g_pos[b * L_ + l + 3] = base + c[0] + c[1] + c[2];

    if (tid == 0) g_cnt[b] = cnt;
    for (int j = cnt + tid; j < L_; j += 256) g_idx[b * L_ + j] = 0;
    for (int j = cnt2 + tid; j < L_; j += 256) g_idx2[b * L_ + j] = 0;
}

// ---------------------------------------------------------------------------
// conv: split x into bf16 hi/lo, plus COMPACT transposed copies.
// ---------------------------------------------------------------------------
__global__ __launch_bounds__(256) void conv_kernel(const float* __restrict__ x,
                                                   const int* __restrict__ xmask)
{
    __shared__ bf16 sh[32][33];
    __shared__ bf16 sl[32][33];
    const int b = blockIdx.z;
    const int d0 = blockIdx.x * 32, l0 = blockIdx.y * 32;
    const int tx = threadIdx.x, ty = threadIdx.y;
    const float* X = x + (size_t)b * L_ * D_;
    const size_t bo = (size_t)b * L_ * D_;

#pragma unroll
    for (int i = 0; i < 4; i++) {
        int row = ty + i * 8;
        float v = X[(size_t)(l0 + row) * D_ + d0 + tx];
        bf16 h = __float2bfloat16(v);
        bf16 l = __float2bfloat16(v - __bfloat162float(h));
        size_t o = bo + (size_t)(l0 + row) * D_ + d0 + tx;
        g_xh[o] = h; g_xl[o] = l;
        sh[row][tx] = h; sl[row][tx] = l;
    }
    __syncthreads();
    const int l = l0 + tx;
    const int valid = xmask[b * L_ + l];
    const int col = g_pos[b * L_ + l];
    if (valid != 0) {
#pragma unroll
        for (int i = 0; i < 4; i++) {
            int row = ty + i * 8;
            size_t o = bo + (size_t)(d0 + row) * L_ + col;
            g_xtch[o] = sh[tx][row];
            g_xtcl[o] = sl[tx][row];
        }
    }
}

// pad_zero: zero the compact-transpose pad columns [cnt, cntpad32)
__global__ __launch_bounds__(256) void pad_zero()
{
    const int b = blockIdx.x;
    const int cnt = g_cnt[b];
    const int cp = (cnt + 31) & ~31;
    const int w = cp - cnt;
    if (w == 0) return;
    const size_t bo = (size_t)b * L_ * D_;
    for (int t = threadIdx.x; t < w * 1024; t += 256) {
        int j = cnt + t % w;
        int d = t / w;
        g_xtch[bo + (size_t)d * L_ + j] = __float2bfloat16(0.f);
        g_xtcl[bo + (size_t)d * L_ + j] = __float2bfloat16(0.f);
    }
}

// ===========================================================================
// Shared GEMM machinery: 128x128 tile, 8 warps, KC=32 2-stage ring, 2 CTA/SM.
// ===========================================================================
#define KC 32
#define TROW 40                         // elements per smem row (80 bytes)
#define TILE_BYTES (128 * TROW * 2)     // 10240
#define STAGE_BYTES (4 * TILE_BYTES)    // 40960: Ah, Al, Bh, Bl
#define SMEM_SC (2 * STAGE_BYTES)       // 81920 >= 128*129*4 transpose stage

__device__ __forceinline__ void fill_tile128_gather(uint32_t dst, const bf16* __restrict__ src,
                                                    const int* __restrict__ idxp,
                                                    int base, int k0, int tid)
{
#pragma unroll
    for (int i = 0; i < 2; i++) {
        int idx = i * 256 + tid;
        int row = idx >> 2, seg = idx & 3;
        int gr = idxp[base + row];
        cp16(dst + row * 80 + seg * 16,
             src + (size_t)gr * 1024 + k0 + seg * 8);
    }
}

// Mainloop macro body shared by the two scores kernels.
struct Frag { float acc[4][4][4]; };

__device__ __forceinline__ void gemm_mainloop(
    uint32_t sb, const bf16* Ah, const bf16* Al,
    const int* idxA, int rowBase, const int* idxB, int colBase,
    int tid, Frag& f)
{
    const int wid = tid >> 5, lane = tid & 31;
    const int wr = wid >> 2, wc = wid & 3;
    const uint32_t aRowOff = (uint32_t)(wr * 64 + (lane & 15)) * 80;
    const uint32_t aColSel = (uint32_t)(lane >> 4) * 8;
    const uint32_t bRowBase = (uint32_t)(wc * 32 + ((lane >> 4) << 3) + (lane & 7));
    const uint32_t bColSel = (uint32_t)((lane >> 3) & 1) * 8;

#pragma unroll
    for (int i = 0; i < 4; i++)
#pragma unroll
        for (int j = 0; j < 4; j++)
#pragma unroll
            for (int k = 0; k < 4; k++) f.acc[i][j][k] = 0.f;

#pragma unroll
    for (int s = 0; s < 2; s++) {
        uint32_t st = sb + s * STAGE_BYTES;
        fill_tile128_gather(st + 0 * TILE_BYTES, Ah, idxA, rowBase, s * KC, tid);
        fill_tile128_gather(st + 1 * TILE_BYTES, Al, idxA, rowBase, s * KC, tid);
        fill_tile128_gather(st + 2 * TILE_BYTES, Ah, idxB, colBase, s * KC, tid);
        fill_tile128_gather(st + 3 * TILE_BYTES, Al, idxB, colBase, s * KC, tid);
        CP_COMMIT();
    }

    for (int c = 0; c < 32; c++) {
        if (c >= 30) CP_WAIT0(); else CP_WAIT1();
        __syncthreads();
        const uint32_t st = sb + (c & 1) * STAGE_BYTES;

#pragma unroll
        for (int kk = 0; kk < KC; kk += 16) {
            uint32_t bh[2][4], bl[2][4];
#pragma unroll
            for (int n2 = 0; n2 < 2; n2++) {
                uint32_t off = (bRowBase + (uint32_t)n2 * 16) * 80 + (kk + bColSel) * 2;
                ldsm4(bh[n2], st + 2 * TILE_BYTES + off);
                ldsm4(bl[n2], st + 3 * TILE_BYTES + off);
            }
#pragma unroll
            for (int mf = 0; mf < 4; mf++) {
                uint32_t ah[4], al[4];
                uint32_t off = aRowOff + (uint32_t)mf * (16 * 80) + (kk + aColSel) * 2;
                ldsm4(ah, st + 0 * TILE_BYTES + off);
                ldsm4(al, st + 1 * TILE_BYTES + off);
#pragma unroll
                for (int nf = 0; nf < 4; nf++) {
                    const uint32_t* bhp = &bh[nf >> 1][(nf & 1) * 2];
                    const uint32_t* blp = &bl[nf >> 1][(nf & 1) * 2];
                    mma16816(f.acc[mf][nf], ah, bhp);
                    mma16816(f.acc[mf][nf], al, bhp);
                    mma16816(f.acc[mf][nf], ah, blp);
                }
            }
        }
        __syncthreads();
        if (c + 2 < 32) {
            const int k0 = (c + 2) * KC;
            fill_tile128_gather(st + 0 * TILE_BYTES, Ah, idxA, rowBase, k0, tid);
            fill_tile128_gather(st + 1 * TILE_BYTES, Al, idxA, rowBase, k0, tid);
            fill_tile128_gather(st + 2 * TILE_BYTES, Ah, idxB, colBase, k0, tid);
            fill_tile128_gather(st + 3 * TILE_BYTES, Al, idxB, colBase, k0, tid);
            CP_COMMIT();
        }
    }
}

// ===========================================================================
// scores_sym: valid rows x compact cols, triangular (bi >= bj), dual write.
// G[i,j] (compact coords) is symmetric; compact diag == original diag.
// ===========================================================================
__global__ __launch_bounds__(256, 2) void scores_sym()
{
    extern __shared__ char smem[];
    const uint32_t sb = smem_u32(smem);
    float* ss = (float*)smem;
    const int tid = threadIdx.x;
    const int wid = tid >> 5, lane = tid & 31;
    const int wr = wid >> 2, wc = wid & 3;
    const int b = blockIdx.z;
    const int cnt = g_cnt[b];

    const int t = blockIdx.x;
    int bi = 0, a0 = 0;
    while (a0 + bi + 1 <= t) { bi++; a0 += bi; }
    const int bj = t - a0;
    const int rowBase = bi * 128;
    const int colBase = bj * 128;
    if (rowBase >= cnt) return;

    const size_t bo = (size_t)b * 1024 * 1024;
    const int* idxp = g_idx + b * L_;
    float* O = g_scores + bo;

    Frag f;
    gemm_mainloop(sb, g_xh + bo, g_xl + bo, idxp, rowBase, idxp, colBase, tid, f);

    // direct write: S[idx[rowBase+rl]][colBase+cl], zero iff compact i==j
    const int rb0 = wr * 64 + (lane >> 2);
    const int cb0 = wc * 32 + (lane & 3) * 2;
#pragma unroll
    for (int mf = 0; mf < 4; mf++) {
        const int rl = rb0 + mf * 16;
#pragma unroll
        for (int nf = 0; nf < 4; nf++) {
            const int cl = cb0 + nf * 8;
            const int i0 = rowBase + rl, i8 = i0 + 8;
            const int j = colBase + cl;
            if (i0 < cnt) {
                float v0 = (i0 == j) ? 0.f : f.acc[mf][nf][0];
                float v1 = (i0 == j + 1) ? 0.f : f.acc[mf][nf][1];
                *(float2*)(O + (size_t)idxp[i0] * 1024 + j) = make_float2(v0, v1);
            }
            if (i8 < cnt) {
                float v2 = (i8 == j) ? 0.f : f.acc[mf][nf][2];
                float v3 = (i8 == j + 1) ? 0.f : f.acc[mf][nf][3];
                *(float2*)(O + (size_t)idxp[i8] * 1024 + j) = make_float2(v2, v3);
            }
        }
    }

    if (bi == bj) return;

    // stage raw tile, write transposed: S[idx[colBase+cl]][rowBase+rl]
    __syncthreads();
#pragma unroll
    for (int mf = 0; mf < 4; mf++) {
        const int rl = rb0 + mf * 16;
#pragma unroll
        for (int nf = 0; nf < 4; nf++) {
            const int cl = cb0 + nf * 8;
            ss[rl * 129 + cl]           = f.acc[mf][nf][0];
            ss[rl * 129 + cl + 1]       = f.acc[mf][nf][1];
            ss[(rl + 8) * 129 + cl]     = f.acc[mf][nf][2];
            ss[(rl + 8) * 129 + cl + 1] = f.acc[mf][nf][3];
        }
    }
    __syncthreads();
    {
#pragma unroll
        for (int q = 0; q < 16; q++) {
            const int cl = wid * 16 + q;
            const int j = colBase + cl;
            if (j >= cnt) continue;
            const int grow = g_idx[b * L_ + j];
            const int rl0 = lane * 4;
            float4 v;
            v.x = ss[(rl0 + 0) * 129 + cl];
            v.y = ss[(rl0 + 1) * 129 + cl];
            v.z = ss[(rl0 + 2) * 129 + cl];
            v.w = ss[(rl0 + 3) * 129 + cl];
            // off-diag tiles (bi>bj) can't contain the compact diag
            *(float4*)(O + (size_t)grow * 1024 + rowBase + rl0) = v;
        }
    }
}

// ===========================================================================
// scores_rect: invalid rows x compact cols. No diag/mask zeroing possible.
// ===========================================================================
__global__ __launch_bounds__(256, 2) void scores_rect()
{
    extern __shared__ char smem[];
    const uint32_t sb = smem_u32(smem);
    const int tid = threadIdx.x;
    const int wid = tid >> 5, lane = tid & 31;
    const int wr = wid >> 2, wc = wid & 3;
    const int b = blockIdx.z;
    const int cnt = g_cnt[b];
    const int cnt2 = L_ - cnt;
    const int rowBase = blockIdx.y * 128;
    const int colBase = blockIdx.x * 128;
    if (rowBase >= cnt2 || colBase >= cnt) return;

    const size_t bo = (size_t)b * 1024 * 1024;
    const int* idxv = g_idx + b * L_;
    const int* idxi = g_idx2 + b * L_;
    float* O = g_scores + bo;

    Frag f;
    gemm_mainloop(sb, g_xh + bo, g_xl + bo, idxi, rowBase, idxv, colBase, tid, f);

    const int rb0 = wr * 64 + (lane >> 2);
    const int cb0 = wc * 32 + (lane & 3) * 2;
#pragma unroll
    for (int mf = 0; mf < 4; mf++) {
        const int rl = rb0 + mf * 16;
#pragma unroll
        for (int nf = 0; nf < 4; nf++) {
            const int cl = cb0 + nf * 8;
            const int i0 = rowBase + rl, i8 = i0 + 8;
            const int j = colBase + cl;
            if (i0 < cnt2)
                *(float2*)(O + (size_t)idxi[i0] * 1024 + j) =
                    make_float2(f.acc[mf][nf][0], f.acc[mf][nf][1]);
            if (i8 < cnt2)
                *(float2*)(O + (size_t)idxi[i8] * 1024 + j) =
                    make_float2(f.acc[mf][nf][2], f.acc[mf][nf][3]);
        }
    }
}

// ---------------------------------------------------------------------------
// Softmax on compact columns (unchanged from R11).
// ---------------------------------------------------------------------------
__global__ __launch_bounds__(256) void softmax_kernel()
{
    const int row = blockIdx.x;
    const int b = row >> 10;
    const int cnt = g_cnt[b];
    const int cp = (cnt + 31) & ~31;
    const float* srow = g_scores + (size_t)row * L_;
    const int tid = threadIdx.x;
    const int j4 = tid * 4;

    float s[4];
    int pres[4];
    if (j4 + 4 <= cnt) {
        float4 v = *(const float4*)(srow + j4);
        s[0] = v.x; s[1] = v.y; s[2] = v.z; s[3] = v.w;
        pres[0] = pres[1] = pres[2] = pres[3] = 1;
    } else {
#pragma unroll
        for (int k = 0; k < 4; k++) {
            int j = j4 + k;
            pres[k] = (j < cnt);
            s[k] = pres[k] ? srow[j] : 0.f;
        }
    }

    __shared__ float red[8];
    float mx = fmaxf(fmaxf(fmaxf(s[0], s[1]), fmaxf(s[2], s[3])), 0.f);
#pragma unroll
    for (int o = 16; o > 0; o >>= 1) mx = fmaxf(mx, __shfl_xor_sync(0xffffffffu, mx, o));
    if ((tid & 31) == 0) red[tid >> 5] = mx;
    __syncthreads();
    if (tid < 32) {
        float t = (tid < 8) ? red[tid] : 0.f;
#pragma unroll
        for (int o = 4; o > 0; o >>= 1) t = fmaxf(t, __shfl_xor_sync(0xffffffffu, t, o));
        if (tid == 0) red[0] = t;
    }
    __syncthreads();
    mx = red[0];
    __syncthreads();

    float e[4];
#pragma unroll
    for (int k = 0; k < 4; k++) e[k] = pres[k] ? __expf(s[k] - mx) : 0.f;
    float sm = e[0] + e[1] + e[2] + e[3];
#pragma unroll
    for (int o = 16; o > 0; o >>= 1) sm += __shfl_xor_sync(0xffffffffu, sm, o);
    __shared__ float redm[8];
    if ((tid & 31) == 0) redm[tid >> 5] = sm;
    __syncthreads();
    if (tid < 32) {
        float t = (tid < 8) ? redm[tid] : 0.f;
#pragma unroll
        for (int o = 4; o > 0; o >>= 1) t += __shfl_xor_sync(0xffffffffu, t, o);
        if (tid == 0) redm[0] = t;
    }
    __syncthreads();
    sm = redm[0];

    const float denom = sm + 1e-13f * (sm + (float)(L_ - cnt) * __expf(-mx));
    const float inv = 1.f / denom;

    if (j4 < cp) {
        bf16 hh[4], ll[4];
#pragma unroll
        for (int k = 0; k < 4; k++) {
            float a = e[k] * inv;
            hh[k] = __float2bfloat16(a);
            ll[k] = __float2bfloat16(a - __bfloat162float(hh[k]));
        }
        const size_t o = (size_t)row * L_ + j4;
        *(uint2*)(g_ah + o) = *(uint2*)hh;
        *(uint2*)(g_al + o) = *(uint2*)ll;
    }
}

// ===========================================================================
// OUT kernel: 256x128 CTA tile, 512 threads, 3-stage ring, runtime K=cntpad32.
// ===========================================================================
#define NSTAGE 3
#define ATILE_B (256 * TROW * 2)        // 20480
#define BTILE_B (128 * TROW * 2)        // 10240
#define AH_OFF 0
#define AL_OFF ATILE_B
#define BH_OFF (2 * ATILE_B)
#define BL_OFF (2 * ATILE_B + BTILE_B)
#define OSTAGE_BYTES (2 * ATILE_B + 2 * BTILE_B)   // 61440
#define SMEM_OUT (NSTAGE * OSTAGE_BYTES)           // 184320

__device__ __forceinline__ void fill_stage_out(uint32_t st,
                                               const bf16* __restrict__ Ah,
                                               const bf16* __restrict__ Al,
                                               const bf16* __restrict__ Bh,
                                               const bf16* __restrict__ Bl,
                                               int rowBase, int colBase, int k0, int tid)
{
#pragma unroll
    for (int i = 0; i < 2; i++) {
        int idx = i * 512 + tid;
        int row = idx >> 2, seg = idx & 3;
        uint32_t d = st + row * 80 + seg * 16;
        size_t so = (size_t)(rowBase + row) * 1024 + k0 + seg * 8;
        cp16(d + AH_OFF, Ah + so);
        cp16(d + AL_OFF, Al + so);
    }
    {
        int row = tid >> 2, seg = tid & 3;
        uint32_t d = st + row * 80 + seg * 16;
        size_t so = (size_t)(colBase + row) * 1024 + k0 + seg * 8;
        cp16(d + BH_OFF, Bh + so);
        cp16(d + BL_OFF, Bl + so);
    }
}

__global__ __launch_bounds__(512, 1) void out_kernel(float* __restrict__ gout)
{
    extern __shared__ char smem[];
    const uint32_t sb = smem_u32(smem);
    const int tid = threadIdx.x;
    const int wid = tid >> 5, lane = tid & 31;
    const int wr = wid >> 2, wc = wid & 3;
    const int b = blockIdx.z;
    const int rowBase = blockIdx.y * 256;
    const int colBase = blockIdx.x * 128;
    const int cnt = g_cnt[b];
    const int nch = (cnt + 31) >> 5;

    const size_t bo = (size_t)b * 1024 * 1024;
    const bf16* Ah = g_ah + bo;
    const bf16* Al = g_al + bo;
    const bf16* Bh = g_xtch + bo;
    const bf16* Bl = g_xtcl + bo;
    float* O = gout + bo;

    float acc[4][4][4];
#pragma unroll
    for (int i = 0; i < 4; i++)
#pragma unroll
        for (int j = 0; j < 4; j++)
#pragma unroll
            for (int k = 0; k < 4; k++) acc[i][j][k] = 0.f;

    const uint32_t aRowOff = (uint32_t)(wr * 64 + (lane & 15)) * 80;
    const uint32_t aColSel = (uint32_t)(lane >> 4) * 8;
    const uint32_t bRowBase = (uint32_t)(wc * 32 + ((lane >> 4) << 3) + (lane & 7));
    const uint32_t bColSel = (uint32_t)((lane >> 3) & 1) * 8;

#pragma unroll
    for (int s = 0; s < NSTAGE - 1; s++) {
        fill_stage_out(sb + s * OSTAGE_BYTES, Ah, Al, Bh, Bl, rowBase, colBase, s * KC, tid);
        CP_COMMIT();
    }

    int s_cur = 0, s_nxt = 2;
    for (int c = 0; c < nch; c++) {
        if (c >= nch - 1) CP_WAIT0(); else CP_WAIT1();
        __syncthreads();
        const uint32_t st = sb + s_cur * OSTAGE_BYTES;

        if (c + NSTAGE - 1 < nch) {
            fill_stage_out(sb + s_nxt * OSTAGE_BYTES, Ah, Al, Bh, Bl,
                           rowBase, colBase, (c + NSTAGE - 1) * KC, tid);
            CP_COMMIT();
        }

#pragma unroll
        for (int kk = 0; kk < KC; kk += 16) {
            uint32_t bh[2][4], bl[2][4];
#pragma unroll
            for (int n2 = 0; n2 < 2; n2++) {
                uint32_t off = (bRowBase + (uint32_t)n2 * 16) * 80 + (kk + bColSel) * 2;
                ldsm4(bh[n2], st + BH_OFF + off);
                ldsm4(bl[n2], st + BL_OFF + off);
            }
#pragma unroll
            for (int mf = 0; mf < 4; mf++) {
                uint32_t ah[4], al[4];
                uint32_t off = aRowOff + (uint32_t)mf * (16 * 80) + (kk + aColSel) * 2;
                ldsm4(ah, st + AH_OFF + off);
                ldsm4(al, st + AL_OFF + off);
#pragma unroll
                for (int nf = 0; nf < 4; nf++) {
                    const uint32_t* bhp = &bh[nf >> 1][(nf & 1) * 2];
                    const uint32_t* blp = &bl[nf >> 1][(nf & 1) * 2];
                    mma16816(acc[mf][nf], ah, bhp);
                    mma16816(acc[mf][nf], al, bhp);
                    mma16816(acc[mf][nf], ah, blp);
                }
            }
        }
        s_cur++; if (s_cur == NSTAGE) s_cur = 0;
        s_nxt++; if (s_nxt == NSTAGE) s_nxt = 0;
    }

    const int rb = rowBase + wr * 64 + (lane >> 2);
    const int cb = colBase + wc * 32 + (lane & 3) * 2;
#pragma unroll
    for (int mf = 0; mf < 4; mf++) {
        const int r = rb + mf * 16;
#pragma unroll
        for (int nf = 0; nf < 4; nf++) {
            const int cc = cb + nf * 8;
            *(float2*)(O + (size_t)r * 1024 + cc) = make_float2(acc[mf][nf][0], acc[mf][nf][1]);
            *(float2*)(O + (size_t)(r + 8) * 1024 + cc) = make_float2(acc[mf][nf][2], acc[mf][nf][3]);
        }
    }
}

// ---------------------------------------------------------------------------
extern "C" void kernel_launch(void* const* d_in, const int* in_sizes, int n_in,
                              void* d_out, int out_size)
{
    const float* x = (const float*)d_in[0];
    const int* xmask = (const int*)d_in[1];
    float* out = (float*)d_out;

    cudaFuncSetAttribute(scores_sym,
                         cudaFuncAttributeMaxDynamicSharedMemorySize, SMEM_SC);
    cudaFuncSetAttribute(scores_rect,
                         cudaFuncAttributeMaxDynamicSharedMemorySize, SMEM_SC);
    cudaFuncSetAttribute(out_kernel,
                         cudaFuncAttributeMaxDynamicSharedMemorySize, SMEM_OUT);

    mask_scan<<<B_, 256>>>(xmask);

    conv_kernel<<<dim3(32, 32, B_), dim3(32, 8)>>>(x, xmask);

    pad_zero<<<B_, 256>>>();

    scores_sym<<<dim3(36, 1, B_), 256, SMEM_SC>>>();
    scores_rect<<<dim3(8, 8, B_), 256, SMEM_SC>>>();

    softmax_kernel<<<B_ * L_, 256>>>();

    out_kernel<<<dim3(8, 4, B_), 512, SMEM_OUT>>>(out);
}

// round 13
// speedup vs baseline: 1.0635x; 1.0635x over previous
#include <cuda_runtime.h>
#include <cuda_bf16.h>
#include <cstdint>

#define B_ 32
#define L_ 1024
#define D_ 1024
typedef __nv_bfloat16 bf16;

// ---------------------------------------------------------------------------
// Scratch (device globals; no allocation in kernel_launch)
// ---------------------------------------------------------------------------
__device__ bf16  g_xh  [(size_t)B_ * L_ * D_];  // x hi split, [b, l, d]
__device__ bf16  g_xl  [(size_t)B_ * L_ * D_];  // x lo split
__device__ bf16  g_xtch[(size_t)B_ * L_ * D_];  // compact x^T hi, [b, d, j]
__device__ bf16  g_xtcl[(size_t)B_ * L_ * D_];  // compact x^T lo
__device__ float g_scores[(size_t)B_ * L_ * L_]; // compact cols [b, r, j<cnt]
__device__ bf16  g_ah  [(size_t)B_ * L_ * L_];  // compact alpha hi
__device__ bf16  g_al  [(size_t)B_ * L_ * L_];  // compact alpha lo
__device__ int   g_idx [B_ * L_];               // valid-row indices (pad 0)
__device__ int   g_idx2[B_ * L_];               // invalid-row indices (pad 0)
__device__ int   g_pos [B_ * L_];               // exclusive prefix of mask
__device__ int   g_cnt [B_];

// ---------------------------------------------------------------------------
// PTX helpers (baseline ISA only — harness targets plain sm_103, no tcgen05)
// ---------------------------------------------------------------------------
__device__ __forceinline__ uint32_t smem_u32(const void* p) {
    uint32_t a;
    asm("{ .reg .u64 t; cvta.to.shared.u64 t, %1; cvt.u32.u64 %0, t; }" : "=r"(a) : "l"(p));
    return a;
}
#define CP_COMMIT() asm volatile("cp.async.commit_group;" ::: "memory")
#define CP_WAIT1()  asm volatile("cp.async.wait_group 1;" ::: "memory")
#define CP_WAIT0()  asm volatile("cp.async.wait_group 0;" ::: "memory")

__device__ __forceinline__ void cp16(uint32_t dst, const void* src) {
    asm volatile("cp.async.cg.shared.global [%0], [%1], 16;" :: "r"(dst), "l"(src));
}
__device__ __forceinline__ void ldsm4(uint32_t* r, uint32_t addr) {
    asm volatile("ldmatrix.sync.aligned.m8n8.x4.shared.b16 {%0,%1,%2,%3}, [%4];"
                 : "=r"(r[0]), "=r"(r[1]), "=r"(r[2]), "=r"(r[3]) : "r"(addr));
}
__device__ __forceinline__ void mma16816(float* c, const uint32_t* a, const uint32_t* b) {
    asm volatile(
        "mma.sync.aligned.m16n8k16.row.col.f32.bf16.bf16.f32 "
        "{%0,%1,%2,%3}, {%4,%5,%6,%7}, {%8,%9}, {%0,%1,%2,%3};"
        : "+f"(c[0]), "+f"(c[1]), "+f"(c[2]), "+f"(c[3])
        : "r"(a[0]), "r"(a[1]), "r"(a[2]), "r"(a[3]), "r"(b[0]), "r"(b[1]));
}

// ---------------------------------------------------------------------------
// mask_scan: per batch, exclusive prefix -> g_pos, g_idx (valid), g_idx2
// (invalid), g_cnt.
// ---------------------------------------------------------------------------
__global__ __launch_bounds__(256) void mask_scan(const int* __restrict__ xmask)
{
    const int b = blockIdx.x;
    const int tid = threadIdx.x;
    const int lane = tid & 31, wid = tid >> 5;
    const int4 m = *(const int4*)(xmask + b * L_ + tid * 4);
    const int c[4] = { (m.x != 0), (m.y != 0), (m.z != 0), (m.w != 0) };
    const int tot = c[0] + c[1] + c[2] + c[3];

    int incl = tot;
#pragma unroll
    for (int o = 1; o < 32; o <<= 1) {
        int v = __shfl_up_sync(0xffffffffu, incl, o);
        if (lane >= o) incl += v;
    }
    __shared__ int ws[8];
    if (lane == 31) ws[wid] = incl;
    __syncthreads();
    if (tid < 8) {
        int v = ws[tid];
#pragma unroll
        for (int o = 1; o < 8; o <<= 1) {
            int u = __shfl_up_sync(0xffu, v, o);
            if (tid >= o) v += u;
        }
        ws[tid] = v;
    }
    __syncthreads();
    int base = (wid > 0 ? ws[wid - 1] : 0) + (incl - tot);
    const int cnt = ws[7];
    const int cnt2 = L_ - cnt;

    const int l = tid * 4;
    int p = base;
#pragma unroll
    for (int k = 0; k < 4; k++) {
        const int lg = l + k;
        if (c[k]) { g_idx[b * L_ + p] = lg; p++; }
        else      { g_idx2[b * L_ + (lg - p)] = lg; }
    }
    g_pos[b * L_ + l + 0] = base;
    g_pos[b * L_ + l + 1] = base + c[0];
    g_pos[b * L_ + l + 2] = base + c[0] + c[1];
    g_pos[b * L_ + l + 3] = base + c[0] + c[1] + c[2];

    if (tid == 0) g_cnt[b] = cnt;
    for (int j = cnt + tid; j < L_; j += 256) g_idx[b * L_ + j] = 0;
    for (int j = cnt2 + tid; j < L_; j += 256) g_idx2[b * L_ + j] = 0;
}

// ---------------------------------------------------------------------------
// conv: split x into bf16 hi/lo, plus COMPACT transposed copies.
// ---------------------------------------------------------------------------
__global__ __launch_bounds__(256) void conv_kernel(const float* __restrict__ x,
                                                   const int* __restrict__ xmask)
{
    __shared__ bf16 sh[32][33];
    __shared__ bf16 sl[32][33];
    const int b = blockIdx.z;
    const int d0 = blockIdx.x * 32, l0 = blockIdx.y * 32;
    const int tx = threadIdx.x, ty = threadIdx.y;
    const float* X = x + (size_t)b * L_ * D_;
    const size_t bo = (size_t)b * L_ * D_;

#pragma unroll
    for (int i = 0; i < 4; i++) {
        int row = ty + i * 8;
        float v = X[(size_t)(l0 + row) * D_ + d0 + tx];
        bf16 h = __float2bfloat16(v);
        bf16 l = __float2bfloat16(v - __bfloat162float(h));
        size_t o = bo + (size_t)(l0 + row) * D_ + d0 + tx;
        g_xh[o] = h; g_xl[o] = l;
        sh[row][tx] = h; sl[row][tx] = l;
    }
    __syncthreads();
    const int l = l0 + tx;
    const int valid = xmask[b * L_ + l];
    const int col = g_pos[b * L_ + l];
    if (valid != 0) {
#pragma unroll
        for (int i = 0; i < 4; i++) {
            int row = ty + i * 8;
            size_t o = bo + (size_t)(d0 + row) * L_ + col;
            g_xtch[o] = sh[tx][row];
            g_xtcl[o] = sl[tx][row];
        }
    }
}

// pad_zero: zero the compact-transpose pad columns [cnt, cntpad32)
__global__ __launch_bounds__(256) void pad_zero()
{
    const int b = blockIdx.x;
    const int cnt = g_cnt[b];
    const int cp = (cnt + 31) & ~31;
    const int w = cp - cnt;
    if (w == 0) return;
    const size_t bo = (size_t)b * L_ * D_;
    for (int t = threadIdx.x; t < w * 1024; t += 256) {
        int j = cnt + t % w;
        int d = t / w;
        g_xtch[bo + (size_t)d * L_ + j] = __float2bfloat16(0.f);
        g_xtcl[bo + (size_t)d * L_ + j] = __float2bfloat16(0.f);
    }
}

// ===========================================================================
// Shared GEMM machinery: 128x128 tile, 8 warps, KC=32 2-stage ring, 2 CTA/SM.
// ===========================================================================
#define KC 32
#define TROW 40                         // elements per smem row (80 bytes)
#define TILE_BYTES (128 * TROW * 2)     // 10240
#define STAGE_BYTES (4 * TILE_BYTES)    // 40960: Ah, Al, Bh, Bl
#define SMEM_SC (2 * STAGE_BYTES)       // 81920 >= 128*129*4 transpose stage

__device__ __forceinline__ void fill_tile128_gather(uint32_t dst, const bf16* __restrict__ src,
                                                    const int* __restrict__ idxp,
                                                    int base, int k0, int tid)
{
#pragma unroll
    for (int i = 0; i < 2; i++) {
        int idx = i * 256 + tid;
        int row = idx >> 2, seg = idx & 3;
        int gr = idxp[base + row];
        cp16(dst + row * 80 + seg * 16,
             src + (size_t)gr * 1024 + k0 + seg * 8);
    }
}

struct Frag { float acc[4][4][4]; };

__device__ __forceinline__ void gemm_mainloop(
    uint32_t sb, const bf16* Ah, const bf16* Al,
    const int* idxA, int rowBase, const int* idxB, int colBase,
    int tid, Frag& f)
{
    const int wid = tid >> 5, lane = tid & 31;
    const int wr = wid >> 2, wc = wid & 3;
    const uint32_t aRowOff = (uint32_t)(wr * 64 + (lane & 15)) * 80;
    const uint32_t aColSel = (uint32_t)(lane >> 4) * 8;
    const uint32_t bRowBase = (uint32_t)(wc * 32 + ((lane >> 4) << 3) + (lane & 7));
    const uint32_t bColSel = (uint32_t)((lane >> 3) & 1) * 8;

#pragma unroll
    for (int i = 0; i < 4; i++)
#pragma unroll
        for (int j = 0; j < 4; j++)
#pragma unroll
            for (int k = 0; k < 4; k++) f.acc[i][j][k] = 0.f;

#pragma unroll
    for (int s = 0; s < 2; s++) {
        uint32_t st = sb + s * STAGE_BYTES;
        fill_tile128_gather(st + 0 * TILE_BYTES, Ah, idxA, rowBase, s * KC, tid);
        fill_tile128_gather(st + 1 * TILE_BYTES, Al, idxA, rowBase, s * KC, tid);
        fill_tile128_gather(st + 2 * TILE_BYTES, Ah, idxB, colBase, s * KC, tid);
        fill_tile128_gather(st + 3 * TILE_BYTES, Al, idxB, colBase, s * KC, tid);
        CP_COMMIT();
    }

    for (int c = 0; c < 32; c++) {
        if (c >= 30) CP_WAIT0(); else CP_WAIT1();
        __syncthreads();
        const uint32_t st = sb + (c & 1) * STAGE_BYTES;

#pragma unroll
        for (int kk = 0; kk < KC; kk += 16) {
            uint32_t bh[2][4], bl[2][4];
#pragma unroll
            for (int n2 = 0; n2 < 2; n2++) {
                uint32_t off = (bRowBase + (uint32_t)n2 * 16) * 80 + (kk + bColSel) * 2;
                ldsm4(bh[n2], st + 2 * TILE_BYTES + off);
                ldsm4(bl[n2], st + 3 * TILE_BYTES + off);
            }
#pragma unroll
            for (int mf = 0; mf < 4; mf++) {
                uint32_t ah[4], al[4];
                uint32_t off = aRowOff + (uint32_t)mf * (16 * 80) + (kk + aColSel) * 2;
                ldsm4(ah, st + 0 * TILE_BYTES + off);
                ldsm4(al, st + 1 * TILE_BYTES + off);
#pragma unroll
                for (int nf = 0; nf < 4; nf++) {
                    const uint32_t* bhp = &bh[nf >> 1][(nf & 1) * 2];
                    const uint32_t* blp = &bl[nf >> 1][(nf & 1) * 2];
                    mma16816(f.acc[mf][nf], ah, bhp);
                    mma16816(f.acc[mf][nf], al, bhp);
                    mma16816(f.acc[mf][nf], ah, blp);
                }
            }
        }
        __syncthreads();
        if (c + 2 < 32) {
            const int k0 = (c + 2) * KC;
            fill_tile128_gather(st + 0 * TILE_BYTES, Ah, idxA, rowBase, k0, tid);
            fill_tile128_gather(st + 1 * TILE_BYTES, Al, idxA, rowBase, k0, tid);
            fill_tile128_gather(st + 2 * TILE_BYTES, Ah, idxB, colBase, k0, tid);
            fill_tile128_gather(st + 3 * TILE_BYTES, Al, idxB, colBase, k0, tid);
            CP_COMMIT();
        }
    }
}

// ===========================================================================
// scores_all: ONE launch covering both parts.
//   blockIdx.x <  36 : sym tile (triangular bi>=bj over valid rows), dual write
//   blockIdx.x >= 36 : rect tile (invalid rows x compact cols)
// ===========================================================================
__global__ __launch_bounds__(256, 2) void scores_all()
{
    extern __shared__ char smem[];
    const uint32_t sb = smem_u32(smem);
    float* ss = (float*)smem;
    const int tid = threadIdx.x;
    const int wid = tid >> 5, lane = tid & 31;
    const int wr = wid >> 2, wc = wid & 3;
    const int b = blockIdx.z;
    const int cnt = g_cnt[b];
    const size_t bo = (size_t)b * 1024 * 1024;
    float* O = g_scores + bo;
    const int* idxv = g_idx + b * L_;

    const int rb0 = wr * 64 + (lane >> 2);
    const int cb0 = wc * 32 + (lane & 3) * 2;

    if (blockIdx.x < 36) {
        // ---- sym part ----
        const int t = blockIdx.x;
        int bi = 0, a0 = 0;
        while (a0 + bi + 1 <= t) { bi++; a0 += bi; }
        const int bj = t - a0;
        const int rowBase = bi * 128;
        const int colBase = bj * 128;
        if (rowBase >= cnt) return;

        Frag f;
        gemm_mainloop(sb, g_xh + bo, g_xl + bo, idxv, rowBase, idxv, colBase, tid, f);

        // direct write: S[idx[rowBase+rl]][colBase+cl], zero iff compact i==j
#pragma unroll
        for (int mf = 0; mf < 4; mf++) {
            const int rl = rb0 + mf * 16;
#pragma unroll
            for (int nf = 0; nf < 4; nf++) {
                const int cl = cb0 + nf * 8;
                const int i0 = rowBase + rl, i8 = i0 + 8;
                const int j = colBase + cl;
                if (i0 < cnt) {
                    float v0 = (i0 == j) ? 0.f : f.acc[mf][nf][0];
                    float v1 = (i0 == j + 1) ? 0.f : f.acc[mf][nf][1];
                    *(float2*)(O + (size_t)idxv[i0] * 1024 + j) = make_float2(v0, v1);
                }
                if (i8 < cnt) {
                    float v2 = (i8 == j) ? 0.f : f.acc[mf][nf][2];
                    float v3 = (i8 == j + 1) ? 0.f : f.acc[mf][nf][3];
                    *(float2*)(O + (size_t)idxv[i8] * 1024 + j) = make_float2(v2, v3);
                }
            }
        }

        if (bi == bj) return;

        // stage raw tile, write transposed: S[idx[colBase+cl]][rowBase+rl]
        __syncthreads();
#pragma unroll
        for (int mf = 0; mf < 4; mf++) {
            const int rl = rb0 + mf * 16;
#pragma unroll
            for (int nf = 0; nf < 4; nf++) {
                const int cl = cb0 + nf * 8;
                ss[rl * 129 + cl]           = f.acc[mf][nf][0];
                ss[rl * 129 + cl + 1]       = f.acc[mf][nf][1];
                ss[(rl + 8) * 129 + cl]     = f.acc[mf][nf][2];
                ss[(rl + 8) * 129 + cl + 1] = f.acc[mf][nf][3];
            }
        }
        __syncthreads();
#pragma unroll
        for (int q = 0; q < 16; q++) {
            const int cl = wid * 16 + q;
            const int j = colBase + cl;
            if (j >= cnt) continue;
            const int grow = idxv[j];
            const int rl0 = lane * 4;
            float4 v;
            v.x = ss[(rl0 + 0) * 129 + cl];
            v.y = ss[(rl0 + 1) * 129 + cl];
            v.z = ss[(rl0 + 2) * 129 + cl];
            v.w = ss[(rl0 + 3) * 129 + cl];
            // off-diag tiles (bi>bj) can't contain the compact diag
            *(float4*)(O + (size_t)grow * 1024 + rowBase + rl0) = v;
        }
    } else {
        // ---- rect part ----
        const int t = blockIdx.x - 36;
        const int cnt2 = L_ - cnt;
        const int rowBase = (t >> 3) * 128;
        const int colBase = (t & 7) * 128;
        if (rowBase >= cnt2 || colBase >= cnt) return;

        const int* idxi = g_idx2 + b * L_;
        Frag f;
        gemm_mainloop(sb, g_xh + bo, g_xl + bo, idxi, rowBase, idxv, colBase, tid, f);

#pragma unroll
        for (int mf = 0; mf < 4; mf++) {
            const int rl = rb0 + mf * 16;
#pragma unroll
            for (int nf = 0; nf < 4; nf++) {
                const int cl = cb0 + nf * 8;
                const int i0 = rowBase + rl, i8 = i0 + 8;
                const int j = colBase + cl;
                if (i0 < cnt2)
                    *(float2*)(O + (size_t)idxi[i0] * 1024 + j) =
                        make_float2(f.acc[mf][nf][0], f.acc[mf][nf][1]);
                if (i8 < cnt2)
                    *(float2*)(O + (size_t)idxi[i8] * 1024 + j) =
                        make_float2(f.acc[mf][nf][2], f.acc[mf][nf][3]);
            }
        }
    }
}

// ---------------------------------------------------------------------------
// Softmax on compact columns (unchanged).
// ---------------------------------------------------------------------------
__global__ __launch_bounds__(256) void softmax_kernel()
{
    const int row = blockIdx.x;
    const int b = row >> 10;
    const int cnt = g_cnt[b];
    const int cp = (cnt + 31) & ~31;
    const float* srow = g_scores + (size_t)row * L_;
    const int tid = threadIdx.x;
    const int j4 = tid * 4;

    float s[4];
    int pres[4];
    if (j4 + 4 <= cnt) {
        float4 v = *(const float4*)(srow + j4);
        s[0] = v.x; s[1] = v.y; s[2] = v.z; s[3] = v.w;
        pres[0] = pres[1] = pres[2] = pres[3] = 1;
    } else {
#pragma unroll
        for (int k = 0; k < 4; k++) {
            int j = j4 + k;
            pres[k] = (j < cnt);
            s[k] = pres[k] ? srow[j] : 0.f;
        }
    }

    __shared__ float red[8];
    float mx = fmaxf(fmaxf(fmaxf(s[0], s[1]), fmaxf(s[2], s[3])), 0.f);
#pragma unroll
    for (int o = 16; o > 0; o >>= 1) mx = fmaxf(mx, __shfl_xor_sync(0xffffffffu, mx, o));
    if ((tid & 31) == 0) red[tid >> 5] = mx;
    __syncthreads();
    if (tid < 32) {
        float t = (tid < 8) ? red[tid] : 0.f;
#pragma unroll
        for (int o = 4; o > 0; o >>= 1) t = fmaxf(t, __shfl_xor_sync(0xffffffffu, t, o));
        if (tid == 0) red[0] = t;
    }
    __syncthreads();
    mx = red[0];
    __syncthreads();

    float e[4];
#pragma unroll
    for (int k = 0; k < 4; k++) e[k] = pres[k] ? __expf(s[k] - mx) : 0.f;
    float sm = e[0] + e[1] + e[2] + e[3];
#pragma unroll
    for (int o = 16; o > 0; o >>= 1) sm += __shfl_xor_sync(0xffffffffu, sm, o);
    __shared__ float redm[8];
    if ((tid & 31) == 0) redm[tid >> 5] = sm;
    __syncthreads();
    if (tid < 32) {
        float t = (tid < 8) ? redm[tid] : 0.f;
#pragma unroll
        for (int o = 4; o > 0; o >>= 1) t += __shfl_xor_sync(0xffffffffu, t, o);
        if (tid == 0) redm[0] = t;
    }
    __syncthreads();
    sm = redm[0];

    const float denom = sm + 1e-13f * (sm + (float)(L_ - cnt) * __expf(-mx));
    const float inv = 1.f / denom;

    if (j4 < cp) {
        bf16 hh[4], ll[4];
#pragma unroll
        for (int k = 0; k < 4; k++) {
            float a = e[k] * inv;
            hh[k] = __float2bfloat16(a);
            ll[k] = __float2bfloat16(a - __bfloat162float(hh[k]));
        }
        const size_t o = (size_t)row * L_ + j4;
        *(uint2*)(g_ah + o) = *(uint2*)hh;
        *(uint2*)(g_al + o) = *(uint2*)ll;
    }
}

// ===========================================================================
// OUT kernel: 256x128 CTA tile, 512 threads, 3-stage ring, runtime K=cntpad32.
// ===========================================================================
#define NSTAGE 3
#define ATILE_B (256 * TROW * 2)        // 20480
#define BTILE_B (128 * TROW * 2)        // 10240
#define AH_OFF 0
#define AL_OFF ATILE_B
#define BH_OFF (2 * ATILE_B)
#define BL_OFF (2 * ATILE_B + BTILE_B)
#define OSTAGE_BYTES (2 * ATILE_B + 2 * BTILE_B)   // 61440
#define SMEM_OUT (NSTAGE * OSTAGE_BYTES)           // 184320

__device__ __forceinline__ void fill_stage_out(uint32_t st,
                                               const bf16* __restrict__ Ah,
                                               const bf16* __restrict__ Al,
                                               const bf16* __restrict__ Bh,
                                               const bf16* __restrict__ Bl,
                                               int rowBase, int colBase, int k0, int tid)
{
#pragma unroll
    for (int i = 0; i < 2; i++) {
        int idx = i * 512 + tid;
        int row = idx >> 2, seg = idx & 3;
        uint32_t d = st + row * 80 + seg * 16;
        size_t so = (size_t)(rowBase + row) * 1024 + k0 + seg * 8;
        cp16(d + AH_OFF, Ah + so);
        cp16(d + AL_OFF, Al + so);
    }
    {
        int row = tid >> 2, seg = tid & 3;
        uint32_t d = st + row * 80 + seg * 16;
        size_t so = (size_t)(colBase + row) * 1024 + k0 + seg * 8;
        cp16(d + BH_OFF, Bh + so);
        cp16(d + BL_OFF, Bl + so);
    }
}

__global__ __launch_bounds__(512, 1) void out_kernel(float* __restrict__ gout)
{
    extern __shared__ char smem[];
    const uint32_t sb = smem_u32(smem);
    const int tid = threadIdx.x;
    const int wid = tid >> 5, lane = tid & 31;
    const int wr = wid >> 2, wc = wid & 3;
    const int b = blockIdx.z;
    const int rowBase = blockIdx.y * 256;
    const int colBase = blockIdx.x * 128;
    const int cnt = g_cnt[b];
    const int nch = (cnt + 31) >> 5;

    const size_t bo = (size_t)b * 1024 * 1024;
    const bf16* Ah = g_ah + bo;
    const bf16* Al = g_al + bo;
    const bf16* Bh = g_xtch + bo;
    const bf16* Bl = g_xtcl + bo;
    float* O = gout + bo;

    float acc[4][4][4];
#pragma unroll
    for (int i = 0; i < 4; i++)
#pragma unroll
        for (int j = 0; j < 4; j++)
#pragma unroll
            for (int k = 0; k < 4; k++) acc[i][j][k] = 0.f;

    const uint32_t aRowOff = (uint32_t)(wr * 64 + (lane & 15)) * 80;
    const uint32_t aColSel = (uint32_t)(lane >> 4) * 8;
    const uint32_t bRowBase = (uint32_t)(wc * 32 + ((lane >> 4) << 3) + (lane & 7));
    const uint32_t bColSel = (uint32_t)((lane >> 3) & 1) * 8;

#pragma unroll
    for (int s = 0; s < NSTAGE - 1; s++) {
        fill_stage_out(sb + s * OSTAGE_BYTES, Ah, Al, Bh, Bl, rowBase, colBase, s * KC, tid);
        CP_COMMIT();
    }

    int s_cur = 0, s_nxt = 2;
    for (int c = 0; c < nch; c++) {
        if (c >= nch - 1) CP_WAIT0(); else CP_WAIT1();
        __syncthreads();
        const uint32_t st = sb + s_cur * OSTAGE_BYTES;

        if (c + NSTAGE - 1 < nch) {
            fill_stage_out(sb + s_nxt * OSTAGE_BYTES, Ah, Al, Bh, Bl,
                           rowBase, colBase, (c + NSTAGE - 1) * KC, tid);
            CP_COMMIT();
        }

#pragma unroll
        for (int kk = 0; kk < KC; kk += 16) {
            uint32_t bh[2][4], bl[2][4];
#pragma unroll
            for (int n2 = 0; n2 < 2; n2++) {
                uint32_t off = (bRowBase + (uint32_t)n2 * 16) * 80 + (kk + bColSel) * 2;
                ldsm4(bh[n2], st + BH_OFF + off);
                ldsm4(bl[n2], st + BL_OFF + off);
            }
#pragma unroll
            for (int mf = 0; mf < 4; mf++) {
                uint32_t ah[4], al[4];
                uint32_t off = aRowOff + (uint32_t)mf * (16 * 80) + (kk + aColSel) * 2;
                ldsm4(ah, st + AH_OFF + off);
                ldsm4(al, st + AL_OFF + off);
#pragma unroll
                for (int nf = 0; nf < 4; nf++) {
                    const uint32_t* bhp = &bh[nf >> 1][(nf & 1) * 2];
                    const uint32_t* blp = &bl[nf >> 1][(nf & 1) * 2];
                    mma16816(acc[mf][nf], ah, bhp);
                    mma16816(acc[mf][nf], al, bhp);
                    mma16816(acc[mf][nf], ah, blp);
                }
            }
        }
        s_cur++; if (s_cur == NSTAGE) s_cur = 0;
        s_nxt++; if (s_nxt == NSTAGE) s_nxt = 0;
    }

    const int rb = rowBase + wr * 64 + (lane >> 2);
    const int cb = colBase + wc * 32 + (lane & 3) * 2;
#pragma unroll
    for (int mf = 0; mf < 4; mf++) {
        const int r = rb + mf * 16;
#pragma unroll
        for (int nf = 0; nf < 4; nf++) {
            const int cc = cb + nf * 8;
            *(float2*)(O + (size_t)r * 1024 + cc) = make_float2(acc[mf][nf][0], acc[mf][nf][1]);
            *(float2*)(O + (size_t)(r + 8) * 1024 + cc) = make_float2(acc[mf][nf][2], acc[mf][nf][3]);
        }
    }
}

// ---------------------------------------------------------------------------
extern "C" void kernel_launch(void* const* d_in, const int* in_sizes, int n_in,
                              void* d_out, int out_size)
{
    const float* x = (const float*)d_in[0];
    const int* xmask = (const int*)d_in[1];
    float* out = (float*)d_out;

    cudaFuncSetAttribute(scores_all,
                         cudaFuncAttributeMaxDynamicSharedMemorySize, SMEM_SC);
    cudaFuncSetAttribute(out_kernel,
                         cudaFuncAttributeMaxDynamicSharedMemorySize, SMEM_OUT);

    mask_scan<<<B_, 256>>>(xmask);

    conv_kernel<<<dim3(32, 32, B_), dim3(32, 8)>>>(x, xmask);

    pad_zero<<<B_, 256>>>();

    scores_all<<<dim3(100, 1, B_), 256, SMEM_SC>>>();

    softmax_kernel<<<B_ * L_, 256>>>();

    out_kernel<<<dim3(8, 4, B_), 512, SMEM_OUT>>>(out);
}

// round 14
// speedup vs baseline: 1.2127x; 1.1403x over previous
#include <cuda_runtime.h>
#include <cuda_fp16.h>
#include <cstdint>

#define B_ 32
#define L_ 1024
#define D_ 1024
typedef __half h16;

// ---------------------------------------------------------------------------
// Scratch (device globals; no allocation in kernel_launch)
// ---------------------------------------------------------------------------
__device__ h16   g_xh  [(size_t)B_ * L_ * D_];  // x hi split (fp16), [b, l, d]
__device__ h16   g_xl  [(size_t)B_ * L_ * D_];  // x lo split
__device__ h16   g_xtch[(size_t)B_ * L_ * D_];  // compact x^T hi, [b, d, j]
__device__ h16   g_xtcl[(size_t)B_ * L_ * D_];  // compact x^T lo
__device__ float g_scores[(size_t)B_ * L_ * L_]; // compact cols [b, r, j<cnt]
__device__ h16   g_a   [(size_t)B_ * L_ * L_];  // compact alpha (single fp16)
__device__ int   g_idx [B_ * L_];               // valid-row indices (pad 0)
__device__ int   g_idx2[B_ * L_];               // invalid-row indices (pad 0)
__device__ int   g_pos [B_ * L_];               // exclusive prefix of mask
__device__ int   g_cnt [B_];

// ---------------------------------------------------------------------------
// PTX helpers (baseline ISA only — harness targets plain sm_103, no tcgen05)
// ---------------------------------------------------------------------------
__device__ __forceinline__ uint32_t smem_u32(const void* p) {
    uint32_t a;
    asm("{ .reg .u64 t; cvta.to.shared.u64 t, %1; cvt.u32.u64 %0, t; }" : "=r"(a) : "l"(p));
    return a;
}
#define CP_COMMIT() asm volatile("cp.async.commit_group;" ::: "memory")
#define CP_WAIT1()  asm volatile("cp.async.wait_group 1;" ::: "memory")
#define CP_WAIT0()  asm volatile("cp.async.wait_group 0;" ::: "memory")

__device__ __forceinline__ void cp16(uint32_t dst, const void* src) {
    asm volatile("cp.async.cg.shared.global [%0], [%1], 16;" :: "r"(dst), "l"(src));
}
__device__ __forceinline__ void ldsm4(uint32_t* r, uint32_t addr) {
    asm volatile("ldmatrix.sync.aligned.m8n8.x4.shared.b16 {%0,%1,%2,%3}, [%4];"
                 : "=r"(r[0]), "=r"(r[1]), "=r"(r[2]), "=r"(r[3]) : "r"(addr));
}
__device__ __forceinline__ void mma16816(float* c, const uint32_t* a, const uint32_t* b) {
    asm volatile(
        "mma.sync.aligned.m16n8k16.row.col.f32.f16.f16.f32 "
        "{%0,%1,%2,%3}, {%4,%5,%6,%7}, {%8,%9}, {%0,%1,%2,%3};"
        : "+f"(c[0]), "+f"(c[1]), "+f"(c[2]), "+f"(c[3])
        : "r"(a[0]), "r"(a[1]), "r"(a[2]), "r"(a[3]), "r"(b[0]), "r"(b[1]));
}

// ---------------------------------------------------------------------------
// mask_scan: per batch, exclusive prefix -> g_pos, g_idx (valid), g_idx2
// (invalid), g_cnt.
// ---------------------------------------------------------------------------
__global__ __launch_bounds__(256) void mask_scan(const int* __restrict__ xmask)
{
    const int b = blockIdx.x;
    const int tid = threadIdx.x;
    const int lane = tid & 31, wid = tid >> 5;
    const int4 m = *(const int4*)(xmask + b * L_ + tid * 4);
    const int c[4] = { (m.x != 0), (m.y != 0), (m.z != 0), (m.w != 0) };
    const int tot = c[0] + c[1] + c[2] + c[3];

    int incl = tot;
#pragma unroll
    for (int o = 1; o < 32; o <<= 1) {
        int v = __shfl_up_sync(0xffffffffu, incl, o);
        if (lane >= o) incl += v;
    }
    __shared__ int ws[8];
    if (lane == 31) ws[wid] = incl;
    __syncthreads();
    if (tid < 8) {
        int v = ws[tid];
#pragma unroll
        for (int o = 1; o < 8; o <<= 1) {
            int u = __shfl_up_sync(0xffu, v, o);
            if (tid >= o) v += u;
        }
        ws[tid] = v;
    }
    __syncthreads();
    int base = (wid > 0 ? ws[wid - 1] : 0) + (incl - tot);
    const int cnt = ws[7];
    const int cnt2 = L_ - cnt;

    const int l = tid * 4;
    int p = base;
#pragma unroll
    for (int k = 0; k < 4; k++) {
        const int lg = l + k;
        if (c[k]) { g_idx[b * L_ + p] = lg; p++; }
        else      { g_idx2[b * L_ + (lg - p)] = lg; }
    }
    g_pos[b * L_ + l + 0] = base;
    g_pos[b * L_ + l + 1] = base + c[0];
    g_pos[b * L_ + l + 2] = base + c[0] + c[1];
    g_pos[b * L_ + l + 3] = base + c[0] + c[1] + c[2];

    if (tid == 0) g_cnt[b] = cnt;
    for (int j = cnt + tid; j < L_; j += 256) g_idx[b * L_ + j] = 0;
    for (int j = cnt2 + tid; j < L_; j += 256) g_idx2[b * L_ + j] = 0;
}

// ---------------------------------------------------------------------------
// conv: split x into fp16 hi/lo, plus COMPACT transposed copies.
// ---------------------------------------------------------------------------
__global__ __launch_bounds__(256) void conv_kernel(const float* __restrict__ x,
                                                   const int* __restrict__ xmask)
{
    __shared__ h16 sh[32][33];
    __shared__ h16 sl[32][33];
    const int b = blockIdx.z;
    const int d0 = blockIdx.x * 32, l0 = blockIdx.y * 32;
    const int tx = threadIdx.x, ty = threadIdx.y;
    const float* X = x + (size_t)b * L_ * D_;
    const size_t bo = (size_t)b * L_ * D_;

#pragma unroll
    for (int i = 0; i < 4; i++) {
        int row = ty + i * 8;
        float v = X[(size_t)(l0 + row) * D_ + d0 + tx];
        h16 h = __float2half_rn(v);
        h16 l = __float2half_rn(v - __half2float(h));
        size_t o = bo + (size_t)(l0 + row) * D_ + d0 + tx;
        g_xh[o] = h; g_xl[o] = l;
        sh[row][tx] = h; sl[row][tx] = l;
    }
    __syncthreads();
    const int l = l0 + tx;
    const int valid = xmask[b * L_ + l];
    const int col = g_pos[b * L_ + l];
    if (valid != 0) {
#pragma unroll
        for (int i = 0; i < 4; i++) {
            int row = ty + i * 8;
            size_t o = bo + (size_t)(d0 + row) * L_ + col;
            g_xtch[o] = sh[tx][row];
            g_xtcl[o] = sl[tx][row];
        }
    }
}

// pad_zero: zero the compact-transpose pad columns [cnt, cntpad32)
__global__ __launch_bounds__(256) void pad_zero()
{
    const int b = blockIdx.x;
    const int cnt = g_cnt[b];
    const int cp = (cnt + 31) & ~31;
    const int w = cp - cnt;
    if (w == 0) return;
    const size_t bo = (size_t)b * L_ * D_;
    for (int t = threadIdx.x; t < w * 1024; t += 256) {
        int j = cnt + t % w;
        int d = t / w;
        g_xtch[bo + (size_t)d * L_ + j] = __float2half_rn(0.f);
        g_xtcl[bo + (size_t)d * L_ + j] = __float2half_rn(0.f);
    }
}

// ===========================================================================
// Shared GEMM machinery: 128x128 tile, 8 warps, KC=32 2-stage ring, 2 CTA/SM.
// ===========================================================================
#define KC 32
#define TROW 40                         // elements per smem row (80 bytes)
#define TILE_BYTES (128 * TROW * 2)     // 10240
#define STAGE_BYTES (4 * TILE_BYTES)    // 40960: Ah, Al, Bh, Bl
#define SMEM_SC (2 * STAGE_BYTES)       // 81920 >= 128*129*4 transpose stage

__device__ __forceinline__ void fill_tile128_gather(uint32_t dst, const h16* __restrict__ src,
                                                    const int* __restrict__ idxp,
                                                    int base, int k0, int tid)
{
#pragma unroll
    for (int i = 0; i < 2; i++) {
        int idx = i * 256 + tid;
        int row = idx >> 2, seg = idx & 3;
        int gr = idxp[base + row];
        cp16(dst + row * 80 + seg * 16,
             src + (size_t)gr * 1024 + k0 + seg * 8);
    }
}

struct Frag { float acc[4][4][4]; };

__device__ __forceinline__ void gemm_mainloop(
    uint32_t sb, const h16* Ah, const h16* Al,
    const int* idxA, int rowBase, const int* idxB, int colBase,
    int tid, Frag& f)
{
    const int wid = tid >> 5, lane = tid & 31;
    const int wr = wid >> 2, wc = wid & 3;
    const uint32_t aRowOff = (uint32_t)(wr * 64 + (lane & 15)) * 80;
    const uint32_t aColSel = (uint32_t)(lane >> 4) * 8;
    const uint32_t bRowBase = (uint32_t)(wc * 32 + ((lane >> 4) << 3) + (lane & 7));
    const uint32_t bColSel = (uint32_t)((lane >> 3) & 1) * 8;

#pragma unroll
    for (int i = 0; i < 4; i++)
#pragma unroll
        for (int j = 0; j < 4; j++)
#pragma unroll
            for (int k = 0; k < 4; k++) f.acc[i][j][k] = 0.f;

#pragma unroll
    for (int s = 0; s < 2; s++) {
        uint32_t st = sb + s * STAGE_BYTES;
        fill_tile128_gather(st + 0 * TILE_BYTES, Ah, idxA, rowBase, s * KC, tid);
        fill_tile128_gather(st + 1 * TILE_BYTES, Al, idxA, rowBase, s * KC, tid);
        fill_tile128_gather(st + 2 * TILE_BYTES, Ah, idxB, colBase, s * KC, tid);
        fill_tile128_gather(st + 3 * TILE_BYTES, Al, idxB, colBase, s * KC, tid);
        CP_COMMIT();
    }

    for (int c = 0; c < 32; c++) {
        if (c >= 30) CP_WAIT0(); else CP_WAIT1();
        __syncthreads();
        const uint32_t st = sb + (c & 1) * STAGE_BYTES;

#pragma unroll
        for (int kk = 0; kk < KC; kk += 16) {
            uint32_t bh[2][4], bl[2][4];
#pragma unroll
            for (int n2 = 0; n2 < 2; n2++) {
                uint32_t off = (bRowBase + (uint32_t)n2 * 16) * 80 + (kk + bColSel) * 2;
                ldsm4(bh[n2], st + 2 * TILE_BYTES + off);
                ldsm4(bl[n2], st + 3 * TILE_BYTES + off);
            }
#pragma unroll
            for (int mf = 0; mf < 4; mf++) {
                uint32_t ah[4], al[4];
                uint32_t off = aRowOff + (uint32_t)mf * (16 * 80) + (kk + aColSel) * 2;
                ldsm4(ah, st + 0 * TILE_BYTES + off);
                ldsm4(al, st + 1 * TILE_BYTES + off);
#pragma unroll
                for (int nf = 0; nf < 4; nf++) {
                    const uint32_t* bhp = &bh[nf >> 1][(nf & 1) * 2];
                    const uint32_t* blp = &bl[nf >> 1][(nf & 1) * 2];
                    mma16816(f.acc[mf][nf], ah, bhp);
                    mma16816(f.acc[mf][nf], al, bhp);
                    mma16816(f.acc[mf][nf], ah, blp);
                }
            }
        }
        __syncthreads();
        if (c + 2 < 32) {
            const int k0 = (c + 2) * KC;
            fill_tile128_gather(st + 0 * TILE_BYTES, Ah, idxA, rowBase, k0, tid);
            fill_tile128_gather(st + 1 * TILE_BYTES, Al, idxA, rowBase, k0, tid);
            fill_tile128_gather(st + 2 * TILE_BYTES, Ah, idxB, colBase, k0, tid);
            fill_tile128_gather(st + 3 * TILE_BYTES, Al, idxB, colBase, k0, tid);
            CP_COMMIT();
        }
    }
}

// ===========================================================================
// scores_all: ONE launch covering both parts.
//   blockIdx.x <  36 : sym tile (triangular bi>=bj over valid rows), dual write
//   blockIdx.x >= 36 : rect tile (invalid rows x compact cols)
// ===========================================================================
__global__ __launch_bounds__(256, 2) void scores_all()
{
    extern __shared__ char smem[];
    const uint32_t sb = smem_u32(smem);
    float* ss = (float*)smem;
    const int tid = threadIdx.x;
    const int wid = tid >> 5, lane = tid & 31;
    const int wr = wid >> 2, wc = wid & 3;
    const int b = blockIdx.z;
    const int cnt = g_cnt[b];
    const size_t bo = (size_t)b * 1024 * 1024;
    float* O = g_scores + bo;
    const int* idxv = g_idx + b * L_;

    const int rb0 = wr * 64 + (lane >> 2);
    const int cb0 = wc * 32 + (lane & 3) * 2;

    if (blockIdx.x < 36) {
        const int t = blockIdx.x;
        int bi = 0, a0 = 0;
        while (a0 + bi + 1 <= t) { bi++; a0 += bi; }
        const int bj = t - a0;
        const int rowBase = bi * 128;
        const int colBase = bj * 128;
        if (rowBase >= cnt) return;

        Frag f;
        gemm_mainloop(sb, g_xh + bo, g_xl + bo, idxv, rowBase, idxv, colBase, tid, f);

#pragma unroll
        for (int mf = 0; mf < 4; mf++) {
            const int rl = rb0 + mf * 16;
#pragma unroll
            for (int nf = 0; nf < 4; nf++) {
                const int cl = cb0 + nf * 8;
                const int i0 = rowBase + rl, i8 = i0 + 8;
                const int j = colBase + cl;
                if (i0 < cnt) {
                    float v0 = (i0 == j) ? 0.f : f.acc[mf][nf][0];
                    float v1 = (i0 == j + 1) ? 0.f : f.acc[mf][nf][1];
                    *(float2*)(O + (size_t)idxv[i0] * 1024 + j) = make_float2(v0, v1);
                }
                if (i8 < cnt) {
                    float v2 = (i8 == j) ? 0.f : f.acc[mf][nf][2];
                    float v3 = (i8 == j + 1) ? 0.f : f.acc[mf][nf][3];
                    *(float2*)(O + (size_t)idxv[i8] * 1024 + j) = make_float2(v2, v3);
                }
            }
        }

        if (bi == bj) return;

        __syncthreads();
#pragma unroll
        for (int mf = 0; mf < 4; mf++) {
            const int rl = rb0 + mf * 16;
#pragma unroll
            for (int nf = 0; nf < 4; nf++) {
                const int cl = cb0 + nf * 8;
                ss[rl * 129 + cl]           = f.acc[mf][nf][0];
                ss[rl * 129 + cl + 1]       = f.acc[mf][nf][1];
                ss[(rl + 8) * 129 + cl]     = f.acc[mf][nf][2];
                ss[(rl + 8) * 129 + cl + 1] = f.acc[mf][nf][3];
            }
        }
        __syncthreads();
#pragma unroll
        for (int q = 0; q < 16; q++) {
            const int cl = wid * 16 + q;
            const int j = colBase + cl;
            if (j >= cnt) continue;
            const int grow = idxv[j];
            const int rl0 = lane * 4;
            float4 v;
            v.x = ss[(rl0 + 0) * 129 + cl];
            v.y = ss[(rl0 + 1) * 129 + cl];
            v.z = ss[(rl0 + 2) * 129 + cl];
            v.w = ss[(rl0 + 3) * 129 + cl];
            *(float4*)(O + (size_t)grow * 1024 + rowBase + rl0) = v;
        }
    } else {
        const int t = blockIdx.x - 36;
        const int cnt2 = L_ - cnt;
        const int rowBase = (t >> 3) * 128;
        const int colBase = (t & 7) * 128;
        if (rowBase >= cnt2 || colBase >= cnt) return;

        const int* idxi = g_idx2 + b * L_;
        Frag f;
        gemm_mainloop(sb, g_xh + bo, g_xl + bo, idxi, rowBase, idxv, colBase, tid, f);

#pragma unroll
        for (int mf = 0; mf < 4; mf++) {
            const int rl = rb0 + mf * 16;
#pragma unroll
            for (int nf = 0; nf < 4; nf++) {
                const int cl = cb0 + nf * 8;
                const int i0 = rowBase + rl, i8 = i0 + 8;
                const int j = colBase + cl;
                if (i0 < cnt2)
                    *(float2*)(O + (size_t)idxi[i0] * 1024 + j) =
                        make_float2(f.acc[mf][nf][0], f.acc[mf][nf][1]);
                if (i8 < cnt2)
                    *(float2*)(O + (size_t)idxi[i8] * 1024 + j) =
                        make_float2(f.acc[mf][nf][2], f.acc[mf][nf][3]);
            }
        }
    }
}

// ---------------------------------------------------------------------------
// Softmax on compact columns; writes SINGLE fp16 alpha (pad zeros to cp).
// ---------------------------------------------------------------------------
__global__ __launch_bounds__(256) void softmax_kernel()
{
    const int row = blockIdx.x;
    const int b = row >> 10;
    const int cnt = g_cnt[b];
    const int cp = (cnt + 31) & ~31;
    const float* srow = g_scores + (size_t)row * L_;
    const int tid = threadIdx.x;
    const int j4 = tid * 4;

    float s[4];
    int pres[4];
    if (j4 + 4 <= cnt) {
        float4 v = *(const float4*)(srow + j4);
        s[0] = v.x; s[1] = v.y; s[2] = v.z; s[3] = v.w;
        pres[0] = pres[1] = pres[2] = pres[3] = 1;
    } else {
#pragma unroll
        for (int k = 0; k < 4; k++) {
            int j = j4 + k;
            pres[k] = (j < cnt);
            s[k] = pres[k] ? srow[j] : 0.f;
        }
    }

    __shared__ float red[8];
    float mx = fmaxf(fmaxf(fmaxf(s[0], s[1]), fmaxf(s[2], s[3])), 0.f);
#pragma unroll
    for (int o = 16; o > 0; o >>= 1) mx = fmaxf(mx, __shfl_xor_sync(0xffffffffu, mx, o));
    if ((tid & 31) == 0) red[tid >> 5] = mx;
    __syncthreads();
    if (tid < 32) {
        float t = (tid < 8) ? red[tid] : 0.f;
#pragma unroll
        for (int o = 4; o > 0; o >>= 1) t = fmaxf(t, __shfl_xor_sync(0xffffffffu, t, o));
        if (tid == 0) red[0] = t;
    }
    __syncthreads();
    mx = red[0];
    __syncthreads();

    float e[4];
#pragma unroll
    for (int k = 0; k < 4; k++) e[k] = pres[k] ? __expf(s[k] - mx) : 0.f;
    float sm = e[0] + e[1] + e[2] + e[3];
#pragma unroll
    for (int o = 16; o > 0; o >>= 1) sm += __shfl_xor_sync(0xffffffffu, sm, o);
    __shared__ float redm[8];
    if ((tid & 31) == 0) redm[tid >> 5] = sm;
    __syncthreads();
    if (tid < 32) {
        float t = (tid < 8) ? redm[tid] : 0.f;
#pragma unroll
        for (int o = 4; o > 0; o >>= 1) t += __shfl_xor_sync(0xffffffffu, t, o);
        if (tid == 0) redm[0] = t;
    }
    __syncthreads();
    sm = redm[0];

    const float denom = sm + 1e-13f * (sm + (float)(L_ - cnt) * __expf(-mx));
    const float inv = 1.f / denom;

    if (j4 < cp) {
        h16 hh[4];
#pragma unroll
        for (int k = 0; k < 4; k++) hh[k] = __float2half_rn(e[k] * inv);
        *(uint2*)(g_a + (size_t)row * L_ + j4) = *(uint2*)hh;
    }
}

// ===========================================================================
// OUT kernel: 256x128 CTA tile, 512 threads, 3-stage ring, runtime K=cntpad32.
// A = single fp16 alpha; B = compact x^T fp16 hi/lo. 2 MMAs per k-step.
// ===========================================================================
#define NSTAGE 3
#define ATILE_B (256 * TROW * 2)        // 20480
#define BTILE_B (128 * TROW * 2)        // 10240
#define A_OFF 0
#define BH_OFF ATILE_B
#define BL_OFF (ATILE_B + BTILE_B)
#define OSTAGE_BYTES (ATILE_B + 2 * BTILE_B)       // 40960
#define SMEM_OUT (NSTAGE * OSTAGE_BYTES)           // 122880

__device__ __forceinline__ void fill_stage_out(uint32_t st,
                                               const h16* __restrict__ A,
                                               const h16* __restrict__ Bh,
                                               const h16* __restrict__ Bl,
                                               int rowBase, int colBase, int k0, int tid)
{
    // A tile: 256 rows x 4 16B-segs = 1024 cp16; 512 threads -> 2 each
#pragma unroll
    for (int i = 0; i < 2; i++) {
        int idx = i * 512 + tid;
        int row = idx >> 2, seg = idx & 3;
        cp16(st + A_OFF + row * 80 + seg * 16,
             A + (size_t)(rowBase + row) * 1024 + k0 + seg * 8);
    }
    // B tiles: 128 rows x 4 segs = 512 each; one per thread per tile
    {
        int row = tid >> 2, seg = tid & 3;
        uint32_t d = st + row * 80 + seg * 16;
        size_t so = (size_t)(colBase + row) * 1024 + k0 + seg * 8;
        cp16(d + BH_OFF, Bh + so);
        cp16(d + BL_OFF, Bl + so);
    }
}

__global__ __launch_bounds__(512, 1) void out_kernel(float* __restrict__ gout)
{
    extern __shared__ char smem[];
    const uint32_t sb = smem_u32(smem);
    const int tid = threadIdx.x;
    const int wid = tid >> 5, lane = tid & 31;
    const int wr = wid >> 2, wc = wid & 3;
    const int b = blockIdx.z;
    const int rowBase = blockIdx.y * 256;
    const int colBase = blockIdx.x * 128;
    const int cnt = g_cnt[b];
    const int nch = (cnt + 31) >> 5;

    const size_t bo = (size_t)b * 1024 * 1024;
    const h16* A = g_a + bo;
    const h16* Bh = g_xtch + bo;
    const h16* Bl = g_xtcl + bo;
    float* O = gout + bo;

    float acc[4][4][4];
#pragma unroll
    for (int i = 0; i < 4; i++)
#pragma unroll
        for (int j = 0; j < 4; j++)
#pragma unroll
            for (int k = 0; k < 4; k++) acc[i][j][k] = 0.f;

    const uint32_t aRowOff = (uint32_t)(wr * 64 + (lane & 15)) * 80;
    const uint32_t aColSel = (uint32_t)(lane >> 4) * 8;
    const uint32_t bRowBase = (uint32_t)(wc * 32 + ((lane >> 4) << 3) + (lane & 7));
    const uint32_t bColSel = (uint32_t)((lane >> 3) & 1) * 8;

#pragma unroll
    for (int s = 0; s < NSTAGE - 1; s++) {
        fill_stage_out(sb + s * OSTAGE_BYTES, A, Bh, Bl, rowBase, colBase, s * KC, tid);
        CP_COMMIT();
    }

    int s_cur = 0, s_nxt = 2;
    for (int c = 0; c < nch; c++) {
        if (c >= nch - 1) CP_WAIT0(); else CP_WAIT1();
        __syncthreads();
        const uint32_t st = sb + s_cur * OSTAGE_BYTES;

        if (c + NSTAGE - 1 < nch) {
            fill_stage_out(sb + s_nxt * OSTAGE_BYTES, A, Bh, Bl,
                           rowBase, colBase, (c + NSTAGE - 1) * KC, tid);
            CP_COMMIT();
        }

#pragma unroll
        for (int kk = 0; kk < KC; kk += 16) {
            uint32_t bh[2][4], bl[2][4];
#pragma unroll
            for (int n2 = 0; n2 < 2; n2++) {
                uint32_t off = (bRowBase + (uint32_t)n2 * 16) * 80 + (kk + bColSel) * 2;
                ldsm4(bh[n2], st + BH_OFF + off);
                ldsm4(bl[n2], st + BL_OFF + off);
            }
#pragma unroll
            for (int mf = 0; mf < 4; mf++) {
                uint32_t ah[4];
                uint32_t off = aRowOff + (uint32_t)mf * (16 * 80) + (kk + aColSel) * 2;
                ldsm4(ah, st + A_OFF + off);
#pragma unroll
                for (int nf = 0; nf < 4; nf++) {
                    const uint32_t* bhp = &bh[nf >> 1][(nf & 1) * 2];
                    const uint32_t* blp = &bl[nf >> 1][(nf & 1) * 2];
                    mma16816(acc[mf][nf], ah, bhp);
                    mma16816(acc[mf][nf], ah, blp);
                }
            }
        }
        s_cur++; if (s_cur == NSTAGE) s_cur = 0;
        s_nxt++; if (s_nxt == NSTAGE) s_nxt = 0;
    }

    const int rb = rowBase + wr * 64 + (lane >> 2);
    const int cb = colBase + wc * 32 + (lane & 3) * 2;
#pragma unroll
    for (int mf = 0; mf < 4; mf++) {
        const int r = rb + mf * 16;
#pragma unroll
        for (int nf = 0; nf < 4; nf++) {
            const int cc = cb + nf * 8;
            *(float2*)(O + (size_t)r * 1024 + cc) = make_float2(acc[mf][nf][0], acc[mf][nf][1]);
            *(float2*)(O + (size_t)(r + 8) * 1024 + cc) = make_float2(acc[mf][nf][2], acc[mf][nf][3]);
        }
    }
}

// ---------------------------------------------------------------------------
extern "C" void kernel_launch(void* const* d_in, const int* in_sizes, int n_in,
                              void* d_out, int out_size)
{
    const float* x = (const float*)d_in[0];
    const int* xmask = (const int*)d_in[1];
    float* out = (float*)d_out;

    cudaFuncSetAttribute(scores_all,
                         cudaFuncAttributeMaxDynamicSharedMemorySize, SMEM_SC);
    cudaFuncSetAttribute(out_kernel,
                         cudaFuncAttributeMaxDynamicSharedMemorySize, SMEM_OUT);

    mask_scan<<<B_, 256>>>(xmask);

    conv_kernel<<<dim3(32, 32, B_), dim3(32, 8)>>>(x, xmask);

    pad_zero<<<B_, 256>>>();

    scores_all<<<dim3(100, 1, B_), 256, SMEM_SC>>>();

    softmax_kernel<<<B_ * L_, 256>>>();

    out_kernel<<<dim3(8, 4, B_), 512, SMEM_OUT>>>(out);
}

// round 15
// speedup vs baseline: 1.3909x; 1.1470x over previous
#include <cuda_runtime.h>
#include <cuda_fp16.h>
#include <cstdint>

#define B_ 32
#define L_ 1024
#define D_ 1024
typedef __half h16;

// ---------------------------------------------------------------------------
// Scratch (device globals; no allocation in kernel_launch)
// ---------------------------------------------------------------------------
__device__ h16   g_xh  [(size_t)B_ * L_ * D_];  // x hi split (fp16), [b, l, d]
__device__ h16   g_xl  [(size_t)B_ * L_ * D_];  // x lo split
__device__ h16   g_xtc [(size_t)B_ * L_ * D_];  // compact x^T single fp16, [b, d, j]
__device__ float g_scores[(size_t)B_ * L_ * L_]; // compact cols [b, r, j<cnt]
__device__ h16   g_a   [(size_t)B_ * L_ * L_];  // compact alpha (single fp16)
__device__ int   g_idx [B_ * L_];               // valid-row indices (pad 0)
__device__ int   g_idx2[B_ * L_];               // invalid-row indices (pad 0)
__device__ int   g_pos [B_ * L_];               // exclusive prefix of mask
__device__ int   g_cnt [B_];

// ---------------------------------------------------------------------------
// PTX helpers (baseline ISA only — harness targets plain sm_103, no tcgen05)
// ---------------------------------------------------------------------------
__device__ __forceinline__ uint32_t smem_u32(const void* p) {
    uint32_t a;
    asm("{ .reg .u64 t; cvta.to.shared.u64 t, %1; cvt.u32.u64 %0, t; }" : "=r"(a) : "l"(p));
    return a;
}
#define CP_COMMIT() asm volatile("cp.async.commit_group;" ::: "memory")
#define CP_WAIT1()  asm volatile("cp.async.wait_group 1;" ::: "memory")
#define CP_WAIT0()  asm volatile("cp.async.wait_group 0;" ::: "memory")

__device__ __forceinline__ void cp16(uint32_t dst, const void* src) {
    asm volatile("cp.async.cg.shared.global [%0], [%1], 16;" :: "r"(dst), "l"(src));
}
__device__ __forceinline__ void ldsm4(uint32_t* r, uint32_t addr) {
    asm volatile("ldmatrix.sync.aligned.m8n8.x4.shared.b16 {%0,%1,%2,%3}, [%4];"
                 : "=r"(r[0]), "=r"(r[1]), "=r"(r[2]), "=r"(r[3]) : "r"(addr));
}
__device__ __forceinline__ void mma16816(float* c, const uint32_t* a, const uint32_t* b) {
    asm volatile(
        "mma.sync.aligned.m16n8k16.row.col.f32.f16.f16.f32 "
        "{%0,%1,%2,%3}, {%4,%5,%6,%7}, {%8,%9}, {%0,%1,%2,%3};"
        : "+f"(c[0]), "+f"(c[1]), "+f"(c[2]), "+f"(c[3])
        : "r"(a[0]), "r"(a[1]), "r"(a[2]), "r"(a[3]), "r"(b[0]), "r"(b[1]));
}

// ---------------------------------------------------------------------------
// mask_scan: per batch, exclusive prefix -> g_pos, g_idx (valid), g_idx2
// (invalid), g_cnt.
// ---------------------------------------------------------------------------
__global__ __launch_bounds__(256) void mask_scan(const int* __restrict__ xmask)
{
    const int b = blockIdx.x;
    const int tid = threadIdx.x;
    const int lane = tid & 31, wid = tid >> 5;
    const int4 m = *(const int4*)(xmask + b * L_ + tid * 4);
    const int c[4] = { (m.x != 0), (m.y != 0), (m.z != 0), (m.w != 0) };
    const int tot = c[0] + c[1] + c[2] + c[3];

    int incl = tot;
#pragma unroll
    for (int o = 1; o < 32; o <<= 1) {
        int v = __shfl_up_sync(0xffffffffu, incl, o);
        if (lane >= o) incl += v;
    }
    __shared__ int ws[8];
    if (lane == 31) ws[wid] = incl;
    __syncthreads();
    if (tid < 8) {
        int v = ws[tid];
#pragma unroll
        for (int o = 1; o < 8; o <<= 1) {
            int u = __shfl_up_sync(0xffu, v, o);
            if (tid >= o) v += u;
        }
        ws[tid] = v;
    }
    __syncthreads();
    int base = (wid > 0 ? ws[wid - 1] : 0) + (incl - tot);
    const int cnt = ws[7];
    const int cnt2 = L_ - cnt;

    const int l = tid * 4;
    int p = base;
#pragma unroll
    for (int k = 0; k < 4; k++) {
        const int lg = l + k;
        if (c[k]) { g_idx[b * L_ + p] = lg; p++; }
        else      { g_idx2[b * L_ + (lg - p)] = lg; }
    }
    g_pos[b * L_ + l + 0] = base;
    g_pos[b * L_ + l + 1] = base + c[0];
    g_pos[b * L_ + l + 2] = base + c[0] + c[1];
    g_pos[b * L_ + l + 3] = base + c[0] + c[1] + c[2];

    if (tid == 0) g_cnt[b] = cnt;
    for (int j = cnt + tid; j < L_; j += 256) g_idx[b * L_ + j] = 0;
    for (int j = cnt2 + tid; j < L_; j += 256) g_idx2[b * L_ + j] = 0;
}

// ---------------------------------------------------------------------------
// conv: split x into fp16 hi/lo (row-major, for scores), plus COMPACT
// transposed SINGLE-fp16 copy (for the out GEMM).
// ---------------------------------------------------------------------------
__global__ __launch_bounds__(256) void conv_kernel(const float* __restrict__ x,
                                                   const int* __restrict__ xmask)
{
    __shared__ h16 sh[32][33];
    const int b = blockIdx.z;
    const int d0 = blockIdx.x * 32, l0 = blockIdx.y * 32;
    const int tx = threadIdx.x, ty = threadIdx.y;
    const float* X = x + (size_t)b * L_ * D_;
    const size_t bo = (size_t)b * L_ * D_;

#pragma unroll
    for (int i = 0; i < 4; i++) {
        int row = ty + i * 8;
        float v = X[(size_t)(l0 + row) * D_ + d0 + tx];
        h16 h = __float2half_rn(v);
        h16 l = __float2half_rn(v - __half2float(h));
        size_t o = bo + (size_t)(l0 + row) * D_ + d0 + tx;
        g_xh[o] = h; g_xl[o] = l;
        sh[row][tx] = h;
    }
    __syncthreads();
    const int l = l0 + tx;
    const int valid = xmask[b * L_ + l];
    const int col = g_pos[b * L_ + l];
    if (valid != 0) {
#pragma unroll
        for (int i = 0; i < 4; i++) {
            int row = ty + i * 8;
            g_xtc[bo + (size_t)(d0 + row) * L_ + col] = sh[tx][row];
        }
    }
}

// pad_zero: zero the compact-transpose pad columns [cnt, cntpad32)
__global__ __launch_bounds__(256) void pad_zero()
{
    const int b = blockIdx.x;
    const int cnt = g_cnt[b];
    const int cp = (cnt + 31) & ~31;
    const int w = cp - cnt;
    if (w == 0) return;
    const size_t bo = (size_t)b * L_ * D_;
    for (int t = threadIdx.x; t < w * 1024; t += 256) {
        int j = cnt + t % w;
        int d = t / w;
        g_xtc[bo + (size_t)d * L_ + j] = __float2half_rn(0.f);
    }
}

// ===========================================================================
// Shared GEMM machinery: 128x128 tile, 8 warps, KC=32 2-stage ring, 2 CTA/SM.
// ===========================================================================
#define KC 32
#define TROW 40                         // elements per smem row (80 bytes)
#define TILE_BYTES (128 * TROW * 2)     // 10240
#define STAGE_BYTES (4 * TILE_BYTES)    // 40960: Ah, Al, Bh, Bl
#define SMEM_SC (2 * STAGE_BYTES)       // 81920 >= 128*129*4 transpose stage

__device__ __forceinline__ void fill_tile128_gather(uint32_t dst, const h16* __restrict__ src,
                                                    const int* __restrict__ idxp,
                                                    int base, int k0, int tid)
{
#pragma unroll
    for (int i = 0; i < 2; i++) {
        int idx = i * 256 + tid;
        int row = idx >> 2, seg = idx & 3;
        int gr = idxp[base + row];
        cp16(dst + row * 80 + seg * 16,
             src + (size_t)gr * 1024 + k0 + seg * 8);
    }
}

struct Frag { float acc[4][4][4]; };

__device__ __forceinline__ void gemm_mainloop(
    uint32_t sb, const h16* Ah, const h16* Al,
    const int* idxA, int rowBase, const int* idxB, int colBase,
    int tid, Frag& f)
{
    const int wid = tid >> 5, lane = tid & 31;
    const int wr = wid >> 2, wc = wid & 3;
    const uint32_t aRowOff = (uint32_t)(wr * 64 + (lane & 15)) * 80;
    const uint32_t aColSel = (uint32_t)(lane >> 4) * 8;
    const uint32_t bRowBase = (uint32_t)(wc * 32 + ((lane >> 4) << 3) + (lane & 7));
    const uint32_t bColSel = (uint32_t)((lane >> 3) & 1) * 8;

#pragma unroll
    for (int i = 0; i < 4; i++)
#pragma unroll
        for (int j = 0; j < 4; j++)
#pragma unroll
            for (int k = 0; k < 4; k++) f.acc[i][j][k] = 0.f;

#pragma unroll
    for (int s = 0; s < 2; s++) {
        uint32_t st = sb + s * STAGE_BYTES;
        fill_tile128_gather(st + 0 * TILE_BYTES, Ah, idxA, rowBase, s * KC, tid);
        fill_tile128_gather(st + 1 * TILE_BYTES, Al, idxA, rowBase, s * KC, tid);
        fill_tile128_gather(st + 2 * TILE_BYTES, Ah, idxB, colBase, s * KC, tid);
        fill_tile128_gather(st + 3 * TILE_BYTES, Al, idxB, colBase, s * KC, tid);
        CP_COMMIT();
    }

    for (int c = 0; c < 32; c++) {
        if (c >= 30) CP_WAIT0(); else CP_WAIT1();
        __syncthreads();
        const uint32_t st = sb + (c & 1) * STAGE_BYTES;

#pragma unroll
        for (int kk = 0; kk < KC; kk += 16) {
            uint32_t bh[2][4], bl[2][4];
#pragma unroll
            for (int n2 = 0; n2 < 2; n2++) {
                uint32_t off = (bRowBase + (uint32_t)n2 * 16) * 80 + (kk + bColSel) * 2;
                ldsm4(bh[n2], st + 2 * TILE_BYTES + off);
                ldsm4(bl[n2], st + 3 * TILE_BYTES + off);
            }
#pragma unroll
            for (int mf = 0; mf < 4; mf++) {
                uint32_t ah[4], al[4];
                uint32_t off = aRowOff + (uint32_t)mf * (16 * 80) + (kk + aColSel) * 2;
                ldsm4(ah, st + 0 * TILE_BYTES + off);
                ldsm4(al, st + 1 * TILE_BYTES + off);
#pragma unroll
                for (int nf = 0; nf < 4; nf++) {
                    const uint32_t* bhp = &bh[nf >> 1][(nf & 1) * 2];
                    const uint32_t* blp = &bl[nf >> 1][(nf & 1) * 2];
                    mma16816(f.acc[mf][nf], ah, bhp);
                    mma16816(f.acc[mf][nf], al, bhp);
                    mma16816(f.acc[mf][nf], ah, blp);
                }
            }
        }
        __syncthreads();
        if (c + 2 < 32) {
            const int k0 = (c + 2) * KC;
            fill_tile128_gather(st + 0 * TILE_BYTES, Ah, idxA, rowBase, k0, tid);
            fill_tile128_gather(st + 1 * TILE_BYTES, Al, idxA, rowBase, k0, tid);
            fill_tile128_gather(st + 2 * TILE_BYTES, Ah, idxB, colBase, k0, tid);
            fill_tile128_gather(st + 3 * TILE_BYTES, Al, idxB, colBase, k0, tid);
            CP_COMMIT();
        }
    }
}

// ===========================================================================
// scores_all: ONE launch covering both parts.
//   blockIdx.x <  36 : sym tile (triangular bi>=bj over valid rows), dual write
//   blockIdx.x >= 36 : rect tile (invalid rows x compact cols)
// ===========================================================================
__global__ __launch_bounds__(256, 2) void scores_all()
{
    extern __shared__ char smem[];
    const uint32_t sb = smem_u32(smem);
    float* ss = (float*)smem;
    const int tid = threadIdx.x;
    const int wid = tid >> 5, lane = tid & 31;
    const int wr = wid >> 2, wc = wid & 3;
    const int b = blockIdx.z;
    const int cnt = g_cnt[b];
    const size_t bo = (size_t)b * 1024 * 1024;
    float* O = g_scores + bo;
    const int* idxv = g_idx + b * L_;

    const int rb0 = wr * 64 + (lane >> 2);
    const int cb0 = wc * 32 + (lane & 3) * 2;

    if (blockIdx.x < 36) {
        const int t = blockIdx.x;
        int bi = 0, a0 = 0;
        while (a0 + bi + 1 <= t) { bi++; a0 += bi; }
        const int bj = t - a0;
        const int rowBase = bi * 128;
        const int colBase = bj * 128;
        if (rowBase >= cnt) return;

        Frag f;
        gemm_mainloop(sb, g_xh + bo, g_xl + bo, idxv, rowBase, idxv, colBase, tid, f);

#pragma unroll
        for (int mf = 0; mf < 4; mf++) {
            const int rl = rb0 + mf * 16;
#pragma unroll
            for (int nf = 0; nf < 4; nf++) {
                const int cl = cb0 + nf * 8;
                const int i0 = rowBase + rl, i8 = i0 + 8;
                const int j = colBase + cl;
                if (i0 < cnt) {
                    float v0 = (i0 == j) ? 0.f : f.acc[mf][nf][0];
                    float v1 = (i0 == j + 1) ? 0.f : f.acc[mf][nf][1];
                    *(float2*)(O + (size_t)idxv[i0] * 1024 + j) = make_float2(v0, v1);
                }
                if (i8 < cnt) {
                    float v2 = (i8 == j) ? 0.f : f.acc[mf][nf][2];
                    float v3 = (i8 == j + 1) ? 0.f : f.acc[mf][nf][3];
                    *(float2*)(O + (size_t)idxv[i8] * 1024 + j) = make_float2(v2, v3);
                }
            }
        }

        if (bi == bj) return;

        __syncthreads();
#pragma unroll
        for (int mf = 0; mf < 4; mf++) {
            const int rl = rb0 + mf * 16;
#pragma unroll
            for (int nf = 0; nf < 4; nf++) {
                const int cl = cb0 + nf * 8;
                ss[rl * 129 + cl]           = f.acc[mf][nf][0];
                ss[rl * 129 + cl + 1]       = f.acc[mf][nf][1];
                ss[(rl + 8) * 129 + cl]     = f.acc[mf][nf][2];
                ss[(rl + 8) * 129 + cl + 1] = f.acc[mf][nf][3];
            }
        }
        __syncthreads();
#pragma unroll
        for (int q = 0; q < 16; q++) {
            const int cl = wid * 16 + q;
            const int j = colBase + cl;
            if (j >= cnt) continue;
            const int grow = idxv[j];
            const int rl0 = lane * 4;
            float4 v;
            v.x = ss[(rl0 + 0) * 129 + cl];
            v.y = ss[(rl0 + 1) * 129 + cl];
            v.z = ss[(rl0 + 2) * 129 + cl];
            v.w = ss[(rl0 + 3) * 129 + cl];
            *(float4*)(O + (size_t)grow * 1024 + rowBase + rl0) = v;
        }
    } else {
        const int t = blockIdx.x - 36;
        const int cnt2 = L_ - cnt;
        const int rowBase = (t >> 3) * 128;
        const int colBase = (t & 7) * 128;
        if (rowBase >= cnt2 || colBase >= cnt) return;

        const int* idxi = g_idx2 + b * L_;
        Frag f;
        gemm_mainloop(sb, g_xh + bo, g_xl + bo, idxi, rowBase, idxv, colBase, tid, f);

#pragma unroll
        for (int mf = 0; mf < 4; mf++) {
            const int rl = rb0 + mf * 16;
#pragma unroll
            for (int nf = 0; nf < 4; nf++) {
                const int cl = cb0 + nf * 8;
                const int i0 = rowBase + rl, i8 = i0 + 8;
                const int j = colBase + cl;
                if (i0 < cnt2)
                    *(float2*)(O + (size_t)idxi[i0] * 1024 + j) =
                        make_float2(f.acc[mf][nf][0], f.acc[mf][nf][1]);
                if (i8 < cnt2)
                    *(float2*)(O + (size_t)idxi[i8] * 1024 + j) =
                        make_float2(f.acc[mf][nf][2], f.acc[mf][nf][3]);
            }
        }
    }
}

// ---------------------------------------------------------------------------
// Softmax on compact columns; writes SINGLE fp16 alpha (pad zeros to cp).
// ---------------------------------------------------------------------------
__global__ __launch_bounds__(256) void softmax_kernel()
{
    const int row = blockIdx.x;
    const int b = row >> 10;
    const int cnt = g_cnt[b];
    const int cp = (cnt + 31) & ~31;
    const float* srow = g_scores + (size_t)row * L_;
    const int tid = threadIdx.x;
    const int j4 = tid * 4;

    float s[4];
    int pres[4];
    if (j4 + 4 <= cnt) {
        float4 v = *(const float4*)(srow + j4);
        s[0] = v.x; s[1] = v.y; s[2] = v.z; s[3] = v.w;
        pres[0] = pres[1] = pres[2] = pres[3] = 1;
    } else {
#pragma unroll
        for (int k = 0; k < 4; k++) {
            int j = j4 + k;
            pres[k] = (j < cnt);
            s[k] = pres[k] ? srow[j] : 0.f;
        }
    }

    __shared__ float red[8];
    float mx = fmaxf(fmaxf(fmaxf(s[0], s[1]), fmaxf(s[2], s[3])), 0.f);
#pragma unroll
    for (int o = 16; o > 0; o >>= 1) mx = fmaxf(mx, __shfl_xor_sync(0xffffffffu, mx, o));
    if ((tid & 31) == 0) red[tid >> 5] = mx;
    __syncthreads();
    if (tid < 32) {
        float t = (tid < 8) ? red[tid] : 0.f;
#pragma unroll
        for (int o = 4; o > 0; o >>= 1) t = fmaxf(t, __shfl_xor_sync(0xffffffffu, t, o));
        if (tid == 0) red[0] = t;
    }
    __syncthreads();
    mx = red[0];
    __syncthreads();

    float e[4];
#pragma unroll
    for (int k = 0; k < 4; k++) e[k] = pres[k] ? __expf(s[k] - mx) : 0.f;
    float sm = e[0] + e[1] + e[2] + e[3];
#pragma unroll
    for (int o = 16; o > 0; o >>= 1) sm += __shfl_xor_sync(0xffffffffu, sm, o);
    __shared__ float redm[8];
    if ((tid & 31) == 0) redm[tid >> 5] = sm;
    __syncthreads();
    if (tid < 32) {
        float t = (tid < 8) ? redm[tid] : 0.f;
#pragma unroll
        for (int o = 4; o > 0; o >>= 1) t += __shfl_xor_sync(0xffffffffu, t, o);
        if (tid == 0) redm[0] = t;
    }
    __syncthreads();
    sm = redm[0];

    const float denom = sm + 1e-13f * (sm + (float)(L_ - cnt) * __expf(-mx));
    const float inv = 1.f / denom;

    if (j4 < cp) {
        h16 hh[4];
#pragma unroll
        for (int k = 0; k < 4; k++) hh[k] = __float2half_rn(e[k] * inv);
        *(uint2*)(g_a + (size_t)row * L_ + j4) = *(uint2*)hh;
    }
}

// ===========================================================================
// OUT kernel: 256x128 CTA tile, 512 threads, 3-stage ring, runtime K=cntpad32.
// A = single fp16 alpha; B = single fp16 compact x^T. ONE MMA per k-step.
// ===========================================================================
#define NSTAGE 3
#define ATILE_B (256 * TROW * 2)        // 20480
#define BTILE_B (128 * TROW * 2)        // 10240
#define A_OFF 0
#define B_OFF ATILE_B
#define OSTAGE_BYTES (ATILE_B + BTILE_B)           // 30720
#define SMEM_OUT (NSTAGE * OSTAGE_BYTES)           // 92160

__device__ __forceinline__ void fill_stage_out(uint32_t st,
                                               const h16* __restrict__ A,
                                               const h16* __restrict__ Bx,
                                               int rowBase, int colBase, int k0, int tid)
{
    // A tile: 256 rows x 4 16B-segs = 1024 cp16; 512 threads -> 2 each
#pragma unroll
    for (int i = 0; i < 2; i++) {
        int idx = i * 512 + tid;
        int row = idx >> 2, seg = idx & 3;
        cp16(st + A_OFF + row * 80 + seg * 16,
             A + (size_t)(rowBase + row) * 1024 + k0 + seg * 8);
    }
    // B tile: 128 rows x 4 segs = 512; one per thread
    {
        int row = tid >> 2, seg = tid & 3;
        cp16(st + B_OFF + row * 80 + seg * 16,
             Bx + (size_t)(colBase + row) * 1024 + k0 + seg * 8);
    }
}

__global__ __launch_bounds__(512, 1) void out_kernel(float* __restrict__ gout)
{
    extern __shared__ char smem[];
    const uint32_t sb = smem_u32(smem);
    const int tid = threadIdx.x;
    const int wid = tid >> 5, lane = tid & 31;
    const int wr = wid >> 2, wc = wid & 3;
    const int b = blockIdx.z;
    const int rowBase = blockIdx.y * 256;
    const int colBase = blockIdx.x * 128;
    const int cnt = g_cnt[b];
    const int nch = (cnt + 31) >> 5;

    const size_t bo = (size_t)b * 1024 * 1024;
    const h16* A = g_a + bo;
    const h16* Bx = g_xtc + bo;
    float* O = gout + bo;

    float acc[4][4][4];
#pragma unroll
    for (int i = 0; i < 4; i++)
#pragma unroll
        for (int j = 0; j < 4; j++)
#pragma unroll
            for (int k = 0; k < 4; k++) acc[i][j][k] = 0.f;

    const uint32_t aRowOff = (uint32_t)(wr * 64 + (lane & 15)) * 80;
    const uint32_t aColSel = (uint32_t)(lane >> 4) * 8;
    const uint32_t bRowBase = (uint32_t)(wc * 32 + ((lane >> 4) << 3) + (lane & 7));
    const uint32_t bColSel = (uint32_t)((lane >> 3) & 1) * 8;

#pragma unroll
    for (int s = 0; s < NSTAGE - 1; s++) {
        fill_stage_out(sb + s * OSTAGE_BYTES, A, Bx, rowBase, colBase, s * KC, tid);
        CP_COMMIT();
    }

    int s_cur = 0, s_nxt = 2;
    for (int c = 0; c < nch; c++) {
        if (c >= nch - 1) CP_WAIT0(); else CP_WAIT1();
        __syncthreads();
        const uint32_t st = sb + s_cur * OSTAGE_BYTES;

        if (c + NSTAGE - 1 < nch) {
            fill_stage_out(sb + s_nxt * OSTAGE_BYTES, A, Bx,
                           rowBase, colBase, (c + NSTAGE - 1) * KC, tid);
            CP_COMMIT();
        }

#pragma unroll
        for (int kk = 0; kk < KC; kk += 16) {
            uint32_t bx[2][4];
#pragma unroll
            for (int n2 = 0; n2 < 2; n2++) {
                uint32_t off = (bRowBase + (uint32_t)n2 * 16) * 80 + (kk + bColSel) * 2;
                ldsm4(bx[n2], st + B_OFF + off);
            }
#pragma unroll
            for (int mf = 0; mf < 4; mf++) {
                uint32_t ah[4];
                uint32_t off = aRowOff + (uint32_t)mf * (16 * 80) + (kk + aColSel) * 2;
                ldsm4(ah, st + A_OFF + off);
#pragma unroll
                for (int nf = 0; nf < 4; nf++) {
                    const uint32_t* bp = &bx[nf >> 1][(nf & 1) * 2];
                    mma16816(acc[mf][nf], ah, bp);
                }
            }
        }
        s_cur++; if (s_cur == NSTAGE) s_cur = 0;
        s_nxt++; if (s_nxt == NSTAGE) s_nxt = 0;
    }

    const int rb = rowBase + wr * 64 + (lane >> 2);
    const int cb = colBase + wc * 32 + (lane & 3) * 2;
#pragma unroll
    for (int mf = 0; mf < 4; mf++) {
        const int r = rb + mf * 16;
#pragma unroll
        for (int nf = 0; nf < 4; nf++) {
            const int cc = cb + nf * 8;
            *(float2*)(O + (size_t)r * 1024 + cc) = make_float2(acc[mf][nf][0], acc[mf][nf][1]);
            *(float2*)(O + (size_t)(r + 8) * 1024 + cc) = make_float2(acc[mf][nf][2], acc[mf][nf][3]);
        }
    }
}

// ---------------------------------------------------------------------------
extern "C" void kernel_launch(void* const* d_in, const int* in_sizes, int n_in,
                              void* d_out, int out_size)
{
    const float* x = (const float*)d_in[0];
    const int* xmask = (const int*)d_in[1];
    float* out = (float*)d_out;

    cudaFuncSetAttribute(scores_all,
                         cudaFuncAttributeMaxDynamicSharedMemorySize, SMEM_SC);
    cudaFuncSetAttribute(out_kernel,
                         cudaFuncAttributeMaxDynamicSharedMemorySize, SMEM_OUT);

    mask_scan<<<B_, 256>>>(xmask);

    conv_kernel<<<dim3(32, 32, B_), dim3(32, 8)>>>(x, xmask);

    pad_zero<<<B_, 256>>>();

    scores_all<<<dim3(100, 1, B_), 256, SMEM_SC>>>();

    softmax_kernel<<<B_ * L_, 256>>>();

    out_kernel<<<dim3(8, 4, B_), 512, SMEM_OUT>>>(out);
}

// round 16
// speedup vs baseline: 1.4277x; 1.0265x over previous
#include <cuda_runtime.h>
#include <cuda_fp16.h>
#include <cstdint>

#define B_ 32
#define L_ 1024
#define D_ 1024
typedef __half h16;

// ---------------------------------------------------------------------------
// Scratch (device globals; no allocation in kernel_launch)
// ---------------------------------------------------------------------------
__device__ h16   g_xh  [(size_t)B_ * L_ * D_];  // x hi split (fp16), [b, l, d]
__device__ h16   g_xl  [(size_t)B_ * L_ * D_];  // x lo split
__device__ h16   g_xtc [(size_t)B_ * L_ * D_];  // compact x^T single fp16, [b, d, j]
__device__ float g_scores[(size_t)B_ * L_ * L_]; // compact cols [b, r, j<cnt]
__device__ h16   g_a   [(size_t)B_ * L_ * L_];  // compact alpha (single fp16)
__device__ int   g_idx [B_ * L_];               // valid-row indices (pad 0)
__device__ int   g_idx2[B_ * L_];               // invalid-row indices (pad 0)
__device__ int   g_pos [B_ * L_];               // exclusive prefix of mask
__device__ int   g_cnt [B_];

// ---------------------------------------------------------------------------
// PTX helpers (baseline ISA only — harness targets plain sm_103, no tcgen05)
// ---------------------------------------------------------------------------
__device__ __forceinline__ uint32_t smem_u32(const void* p) {
    uint32_t a;
    asm("{ .reg .u64 t; cvta.to.shared.u64 t, %1; cvt.u32.u64 %0, t; }" : "=r"(a) : "l"(p));
    return a;
}
#define CP_COMMIT() asm volatile("cp.async.commit_group;" ::: "memory")
#define CP_WAIT1()  asm volatile("cp.async.wait_group 1;" ::: "memory")
#define CP_WAIT0()  asm volatile("cp.async.wait_group 0;" ::: "memory")

__device__ __forceinline__ void cp16(uint32_t dst, const void* src) {
    asm volatile("cp.async.cg.shared.global [%0], [%1], 16;" :: "r"(dst), "l"(src));
}
__device__ __forceinline__ void ldsm4(uint32_t* r, uint32_t addr) {
    asm volatile("ldmatrix.sync.aligned.m8n8.x4.shared.b16 {%0,%1,%2,%3}, [%4];"
                 : "=r"(r[0]), "=r"(r[1]), "=r"(r[2]), "=r"(r[3]) : "r"(addr));
}
__device__ __forceinline__ void mma16816(float* c, const uint32_t* a, const uint32_t* b) {
    asm volatile(
        "mma.sync.aligned.m16n8k16.row.col.f32.f16.f16.f32 "
        "{%0,%1,%2,%3}, {%4,%5,%6,%7}, {%8,%9}, {%0,%1,%2,%3};"
        : "+f"(c[0]), "+f"(c[1]), "+f"(c[2]), "+f"(c[3])
        : "r"(a[0]), "r"(a[1]), "r"(a[2]), "r"(a[3]), "r"(b[0]), "r"(b[1]));
}

// ---------------------------------------------------------------------------
// mask_scan: per batch, exclusive prefix -> g_pos, g_idx (valid), g_idx2
// (invalid), g_cnt.
// ---------------------------------------------------------------------------
__global__ __launch_bounds__(256) void mask_scan(const int* __restrict__ xmask)
{
    const int b = blockIdx.x;
    const int tid = threadIdx.x;
    const int lane = tid & 31, wid = tid >> 5;
    const int4 m = *(const int4*)(xmask + b * L_ + tid * 4);
    const int c[4] = { (m.x != 0), (m.y != 0), (m.z != 0), (m.w != 0) };
    const int tot = c[0] + c[1] + c[2] + c[3];

    int incl = tot;
#pragma unroll
    for (int o = 1; o < 32; o <<= 1) {
        int v = __shfl_up_sync(0xffffffffu, incl, o);
        if (lane >= o) incl += v;
    }
    __shared__ int ws[8];
    if (lane == 31) ws[wid] = incl;
    __syncthreads();
    if (tid < 8) {
        int v = ws[tid];
#pragma unroll
        for (int o = 1; o < 8; o <<= 1) {
            int u = __shfl_up_sync(0xffu, v, o);
            if (tid >= o) v += u;
        }
        ws[tid] = v;
    }
    __syncthreads();
    int base = (wid > 0 ? ws[wid - 1] : 0) + (incl - tot);
    const int cnt = ws[7];
    const int cnt2 = L_ - cnt;

    const int l = tid * 4;
    int p = base;
#pragma unroll
    for (int k = 0; k < 4; k++) {
        const int lg = l + k;
        if (c[k]) { g_idx[b * L_ + p] = lg; p++; }
        else      { g_idx2[b * L_ + (lg - p)] = lg; }
    }
    g_pos[b * L_ + l + 0] = base;
    g_pos[b * L_ + l + 1] = base + c[0];
    g_pos[b * L_ + l + 2] = base + c[0] + c[1];
    g_pos[b * L_ + l + 3] = base + c[0] + c[1] + c[2];

    if (tid == 0) g_cnt[b] = cnt;
    for (int j = cnt + tid; j < L_; j += 256) g_idx[b * L_ + j] = 0;
    for (int j = cnt2 + tid; j < L_; j += 256) g_idx2[b * L_ + j] = 0;
}

// ---------------------------------------------------------------------------
// conv: split x into fp16 hi/lo (row-major; vectorized float4 loads + uint2
// stores), plus COMPACT transposed SINGLE-fp16 copy (for the out GEMM).
// block (32, 8): 32 l-rows x 32 d-cols per block.
// ---------------------------------------------------------------------------
__global__ __launch_bounds__(256) void conv_kernel(const float* __restrict__ x,
                                                   const int* __restrict__ xmask)
{
    __shared__ h16 sh[32][33];
    const int b = blockIdx.z;
    const int d0 = blockIdx.x * 32, l0 = blockIdx.y * 32;
    const int tx = threadIdx.x, ty = threadIdx.y;
    const int t = ty * 32 + tx;
    const float* X = x + (size_t)b * L_ * D_;
    const size_t bo = (size_t)b * L_ * D_;

    // phase 1: each thread one float4 (row = t>>3, 4 d-elems at (t&7)*4)
    {
        const int row = t >> 3;
        const int dc = (t & 7) * 4;
        float4 v = *(const float4*)(X + (size_t)(l0 + row) * D_ + d0 + dc);
        h16 hh[4], ll[4];
        float vv[4] = { v.x, v.y, v.z, v.w };
#pragma unroll
        for (int k = 0; k < 4; k++) {
            hh[k] = __float2half_rn(vv[k]);
            ll[k] = __float2half_rn(vv[k] - __half2float(hh[k]));
            sh[row][dc + k] = hh[k];
        }
        size_t o = bo + (size_t)(l0 + row) * D_ + d0 + dc;
        *(uint2*)(g_xh + o) = *(uint2*)hh;
        *(uint2*)(g_xl + o) = *(uint2*)ll;
    }
    __syncthreads();

    // phase 2: compact transpose (hi only)
    const int l = l0 + tx;
    const int valid = xmask[b * L_ + l];
    const int col = g_pos[b * L_ + l];
    if (valid != 0) {
#pragma unroll
        for (int i = 0; i < 4; i++) {
            int row = ty + i * 8;
            g_xtc[bo + (size_t)(d0 + row) * L_ + col] = sh[tx][row];
        }
    }
}

// pad_zero: zero the compact-transpose pad columns [cnt, cntpad64)
__global__ __launch_bounds__(256) void pad_zero()
{
    const int b = blockIdx.x;
    const int cnt = g_cnt[b];
    const int cp = (cnt + 63) & ~63;
    const int w = cp - cnt;
    if (w == 0) return;
    const size_t bo = (size_t)b * L_ * D_;
    for (int t = threadIdx.x; t < w * 1024; t += 256) {
        int j = cnt + t % w;
        int d = t / w;
        g_xtc[bo + (size_t)d * L_ + j] = __float2half_rn(0.f);
    }
}

// ===========================================================================
// Scores GEMM machinery: 128x128 tile, 8 warps, KC=32 2-stage ring, 2 CTA/SM.
// ===========================================================================
#define KC 32
#define TROW 40                         // elements per smem row (80 bytes)
#define TILE_BYTES (128 * TROW * 2)     // 10240
#define STAGE_BYTES (4 * TILE_BYTES)    // 40960: Ah, Al, Bh, Bl
#define SMEM_SC (2 * STAGE_BYTES)       // 81920 >= 128*129*4 transpose stage

__device__ __forceinline__ void fill_tile128_gather(uint32_t dst, const h16* __restrict__ src,
                                                    const int* __restrict__ idxp,
                                                    int base, int k0, int tid)
{
#pragma unroll
    for (int i = 0; i < 2; i++) {
        int idx = i * 256 + tid;
        int row = idx >> 2, seg = idx & 3;
        int gr = idxp[base + row];
        cp16(dst + row * 80 + seg * 16,
             src + (size_t)gr * 1024 + k0 + seg * 8);
    }
}

struct Frag { float acc[4][4][4]; };

__device__ __forceinline__ void gemm_mainloop(
    uint32_t sb, const h16* Ah, const h16* Al,
    const int* idxA, int rowBase, const int* idxB, int colBase,
    int tid, Frag& f)
{
    const int wid = tid >> 5, lane = tid & 31;
    const int wr = wid >> 2, wc = wid & 3;
    const uint32_t aRowOff = (uint32_t)(wr * 64 + (lane & 15)) * 80;
    const uint32_t aColSel = (uint32_t)(lane >> 4) * 8;
    const uint32_t bRowBase = (uint32_t)(wc * 32 + ((lane >> 4) << 3) + (lane & 7));
    const uint32_t bColSel = (uint32_t)((lane >> 3) & 1) * 8;

#pragma unroll
    for (int i = 0; i < 4; i++)
#pragma unroll
        for (int j = 0; j < 4; j++)
#pragma unroll
            for (int k = 0; k < 4; k++) f.acc[i][j][k] = 0.f;

#pragma unroll
    for (int s = 0; s < 2; s++) {
        uint32_t st = sb + s * STAGE_BYTES;
        fill_tile128_gather(st + 0 * TILE_BYTES, Ah, idxA, rowBase, s * KC, tid);
        fill_tile128_gather(st + 1 * TILE_BYTES, Al, idxA, rowBase, s * KC, tid);
        fill_tile128_gather(st + 2 * TILE_BYTES, Ah, idxB, colBase, s * KC, tid);
        fill_tile128_gather(st + 3 * TILE_BYTES, Al, idxB, colBase, s * KC, tid);
        CP_COMMIT();
    }

    for (int c = 0; c < 32; c++) {
        if (c >= 30) CP_WAIT0(); else CP_WAIT1();
        __syncthreads();
        const uint32_t st = sb + (c & 1) * STAGE_BYTES;

#pragma unroll
        for (int kk = 0; kk < KC; kk += 16) {
            uint32_t bh[2][4], bl[2][4];
#pragma unroll
            for (int n2 = 0; n2 < 2; n2++) {
                uint32_t off = (bRowBase + (uint32_t)n2 * 16) * 80 + (kk + bColSel) * 2;
                ldsm4(bh[n2], st + 2 * TILE_BYTES + off);
                ldsm4(bl[n2], st + 3 * TILE_BYTES + off);
            }
#pragma unroll
            for (int mf = 0; mf < 4; mf++) {
                uint32_t ah[4], al[4];
                uint32_t off = aRowOff + (uint32_t)mf * (16 * 80) + (kk + aColSel) * 2;
                ldsm4(ah, st + 0 * TILE_BYTES + off);
                ldsm4(al, st + 1 * TILE_BYTES + off);
#pragma unroll
                for (int nf = 0; nf < 4; nf++) {
                    const uint32_t* bhp = &bh[nf >> 1][(nf & 1) * 2];
                    const uint32_t* blp = &bl[nf >> 1][(nf & 1) * 2];
                    mma16816(f.acc[mf][nf], ah, bhp);
                    mma16816(f.acc[mf][nf], al, bhp);
                    mma16816(f.acc[mf][nf], ah, blp);
                }
            }
        }
        __syncthreads();
        if (c + 2 < 32) {
            const int k0 = (c + 2) * KC;
            fill_tile128_gather(st + 0 * TILE_BYTES, Ah, idxA, rowBase, k0, tid);
            fill_tile128_gather(st + 1 * TILE_BYTES, Al, idxA, rowBase, k0, tid);
            fill_tile128_gather(st + 2 * TILE_BYTES, Ah, idxB, colBase, k0, tid);
            fill_tile128_gather(st + 3 * TILE_BYTES, Al, idxB, colBase, k0, tid);
            CP_COMMIT();
        }
    }
}

// ===========================================================================
// scores_all: ONE launch covering both parts.
//   blockIdx.x <  36 : sym tile (triangular bi>=bj over valid rows), dual write
//   blockIdx.x >= 36 : rect tile (invalid rows x compact cols)
// ===========================================================================
__global__ __launch_bounds__(256, 2) void scores_all()
{
    extern __shared__ char smem[];
    const uint32_t sb = smem_u32(smem);
    float* ss = (float*)smem;
    const int tid = threadIdx.x;
    const int wid = tid >> 5, lane = tid & 31;
    const int wr = wid >> 2, wc = wid & 3;
    const int b = blockIdx.z;
    const int cnt = g_cnt[b];
    const size_t bo = (size_t)b * 1024 * 1024;
    float* O = g_scores + bo;
    const int* idxv = g_idx + b * L_;

    const int rb0 = wr * 64 + (lane >> 2);
    const int cb0 = wc * 32 + (lane & 3) * 2;

    if (blockIdx.x < 36) {
        const int t = blockIdx.x;
        int bi = 0, a0 = 0;
        while (a0 + bi + 1 <= t) { bi++; a0 += bi; }
        const int bj = t - a0;
        const int rowBase = bi * 128;
        const int colBase = bj * 128;
        if (rowBase >= cnt) return;

        Frag f;
        gemm_mainloop(sb, g_xh + bo, g_xl + bo, idxv, rowBase, idxv, colBase, tid, f);

#pragma unroll
        for (int mf = 0; mf < 4; mf++) {
            const int rl = rb0 + mf * 16;
#pragma unroll
            for (int nf = 0; nf < 4; nf++) {
                const int cl = cb0 + nf * 8;
                const int i0 = rowBase + rl, i8 = i0 + 8;
                const int j = colBase + cl;
                if (i0 < cnt) {
                    float v0 = (i0 == j) ? 0.f : f.acc[mf][nf][0];
                    float v1 = (i0 == j + 1) ? 0.f : f.acc[mf][nf][1];
                    *(float2*)(O + (size_t)idxv[i0] * 1024 + j) = make_float2(v0, v1);
                }
                if (i8 < cnt) {
                    float v2 = (i8 == j) ? 0.f : f.acc[mf][nf][2];
                    float v3 = (i8 == j + 1) ? 0.f : f.acc[mf][nf][3];
                    *(float2*)(O + (size_t)idxv[i8] * 1024 + j) = make_float2(v2, v3);
                }
            }
        }

        if (bi == bj) return;

        __syncthreads();
#pragma unroll
        for (int mf = 0; mf < 4; mf++) {
            const int rl = rb0 + mf * 16;
#pragma unroll
            for (int nf = 0; nf < 4; nf++) {
                const int cl = cb0 + nf * 8;
                ss[rl * 129 + cl]           = f.acc[mf][nf][0];
                ss[rl * 129 + cl + 1]       = f.acc[mf][nf][1];
                ss[(rl + 8) * 129 + cl]     = f.acc[mf][nf][2];
                ss[(rl + 8) * 129 + cl + 1] = f.acc[mf][nf][3];
            }
        }
        __syncthreads();
#pragma unroll
        for (int q = 0; q < 16; q++) {
            const int cl = wid * 16 + q;
            const int j = colBase + cl;
            if (j >= cnt) continue;
            const int grow = idxv[j];
            const int rl0 = lane * 4;
            float4 v;
            v.x = ss[(rl0 + 0) * 129 + cl];
            v.y = ss[(rl0 + 1) * 129 + cl];
            v.z = ss[(rl0 + 2) * 129 + cl];
            v.w = ss[(rl0 + 3) * 129 + cl];
            *(float4*)(O + (size_t)grow * 1024 + rowBase + rl0) = v;
        }
    } else {
        const int t = blockIdx.x - 36;
        const int cnt2 = L_ - cnt;
        const int rowBase = (t >> 3) * 128;
        const int colBase = (t & 7) * 128;
        if (rowBase >= cnt2 || colBase >= cnt) return;

        const int* idxi = g_idx2 + b * L_;
        Frag f;
        gemm_mainloop(sb, g_xh + bo, g_xl + bo, idxi, rowBase, idxv, colBase, tid, f);

#pragma unroll
        for (int mf = 0; mf < 4; mf++) {
            const int rl = rb0 + mf * 16;
#pragma unroll
            for (int nf = 0; nf < 4; nf++) {
                const int cl = cb0 + nf * 8;
                const int i0 = rowBase + rl, i8 = i0 + 8;
                const int j = colBase + cl;
                if (i0 < cnt2)
                    *(float2*)(O + (size_t)idxi[i0] * 1024 + j) =
                        make_float2(f.acc[mf][nf][0], f.acc[mf][nf][1]);
                if (i8 < cnt2)
                    *(float2*)(O + (size_t)idxi[i8] * 1024 + j) =
                        make_float2(f.acc[mf][nf][2], f.acc[mf][nf][3]);
            }
        }
    }
}

// ---------------------------------------------------------------------------
// Softmax on compact columns; writes SINGLE fp16 alpha (pad zeros to cp64).
// ---------------------------------------------------------------------------
__global__ __launch_bounds__(256) void softmax_kernel()
{
    const int row = blockIdx.x;
    const int b = row >> 10;
    const int cnt = g_cnt[b];
    const int cp = (cnt + 63) & ~63;
    const float* srow = g_scores + (size_t)row * L_;
    const int tid = threadIdx.x;
    const int j4 = tid * 4;

    float s[4];
    int pres[4];
    if (j4 + 4 <= cnt) {
        float4 v = *(const float4*)(srow + j4);
        s[0] = v.x; s[1] = v.y; s[2] = v.z; s[3] = v.w;
        pres[0] = pres[1] = pres[2] = pres[3] = 1;
    } else {
#pragma unroll
        for (int k = 0; k < 4; k++) {
            int j = j4 + k;
            pres[k] = (j < cnt);
            s[k] = pres[k] ? srow[j] : 0.f;
        }
    }

    __shared__ float red[8];
    float mx = fmaxf(fmaxf(fmaxf(s[0], s[1]), fmaxf(s[2], s[3])), 0.f);
#pragma unroll
    for (int o = 16; o > 0; o >>= 1) mx = fmaxf(mx, __shfl_xor_sync(0xffffffffu, mx, o));
    if ((tid & 31) == 0) red[tid >> 5] = mx;
    __syncthreads();
    if (tid < 32) {
        float t = (tid < 8) ? red[tid] : 0.f;
#pragma unroll
        for (int o = 4; o > 0; o >>= 1) t = fmaxf(t, __shfl_xor_sync(0xffffffffu, t, o));
        if (tid == 0) red[0] = t;
    }
    __syncthreads();
    mx = red[0];
    __syncthreads();

    float e[4];
#pragma unroll
    for (int k = 0; k < 4; k++) e[k] = pres[k] ? __expf(s[k] - mx) : 0.f;
    float sm = e[0] + e[1] + e[2] + e[3];
#pragma unroll
    for (int o = 16; o > 0; o >>= 1) sm += __shfl_xor_sync(0xffffffffu, sm, o);
    __shared__ float redm[8];
    if ((tid & 31) == 0) redm[tid >> 5] = sm;
    __syncthreads();
    if (tid < 32) {
        float t = (tid < 8) ? redm[tid] : 0.f;
#pragma unroll
        for (int o = 4; o > 0; o >>= 1) t += __shfl_xor_sync(0xffffffffu, t, o);
        if (tid == 0) redm[0] = t;
    }
    __syncthreads();
    sm = redm[0];

    const float denom = sm + 1e-13f * (sm + (float)(L_ - cnt) * __expf(-mx));
    const float inv = 1.f / denom;

    if (j4 < cp) {
        h16 hh[4];
#pragma unroll
        for (int k = 0; k < 4; k++) hh[k] = __float2half_rn(e[k] * inv);
        *(uint2*)(g_a + (size_t)row * L_ + j4) = *(uint2*)hh;
    }
}

// ===========================================================================
// OUT kernel: 256x128 CTA tile, 512 threads, KC=64 chunks, 3-stage ring,
// runtime K. A = single fp16 alpha; B = single fp16 compact x^T.
// 144B smem rows (144 mod 128 = 16 -> ldmatrix conflict-free).
// ===========================================================================
#define KC2 64
#define NSTAGE 3
#define TROW2 72
#define ATILE2 (256 * TROW2 * 2)        // 36864
#define BTILE2 (128 * TROW2 * 2)        // 18432
#define A_OFF 0
#define B_OFF ATILE2
#define OSTAGE_BYTES (ATILE2 + BTILE2)             // 55296
#define SMEM_OUT (NSTAGE * OSTAGE_BYTES)           // 165888

__device__ __forceinline__ void fill_stage_out(uint32_t st,
                                               const h16* __restrict__ A,
                                               const h16* __restrict__ Bx,
                                               int rowBase, int colBase, int k0, int tid)
{
    // A tile: 256 rows x 8 16B-segs = 2048 cp16; 512 threads -> 4 each
#pragma unroll
    for (int i = 0; i < 4; i++) {
        int idx = i * 512 + tid;
        int row = idx >> 3, seg = idx & 7;
        cp16(st + A_OFF + row * 144 + seg * 16,
             A + (size_t)(rowBase + row) * 1024 + k0 + seg * 8);
    }
    // B tile: 128 rows x 8 segs = 1024; 2 per thread
#pragma unroll
    for (int i = 0; i < 2; i++) {
        int idx = i * 512 + tid;
        int row = idx >> 3, seg = idx & 7;
        cp16(st + B_OFF + row * 144 + seg * 16,
             Bx + (size_t)(colBase + row) * 1024 + k0 + seg * 8);
    }
}

__global__ __launch_bounds__(512, 1) void out_kernel(float* __restrict__ gout)
{
    extern __shared__ char smem[];
    const uint32_t sb = smem_u32(smem);
    const int tid = threadIdx.x;
    const int wid = tid >> 5, lane = tid & 31;
    const int wr = wid >> 2, wc = wid & 3;
    const int b = blockIdx.z;
    const int rowBase = blockIdx.y * 256;
    const int colBase = blockIdx.x * 128;
    const int cnt = g_cnt[b];
    const int nch = (cnt + 63) >> 6;

    const size_t bo = (size_t)b * 1024 * 1024;
    const h16* A = g_a + bo;
    const h16* Bx = g_xtc + bo;
    float* O = gout + bo;

    float acc[4][4][4];
#pragma unroll
    for (int i = 0; i < 4; i++)
#pragma unroll
        for (int j = 0; j < 4; j++)
#pragma unroll
            for (int k = 0; k < 4; k++) acc[i][j][k] = 0.f;

    const uint32_t aRowOff = (uint32_t)(wr * 64 + (lane & 15)) * 144;
    const uint32_t aColSel = (uint32_t)(lane >> 4) * 8;
    const uint32_t bRowBase = (uint32_t)(wc * 32 + ((lane >> 4) << 3) + (lane & 7));
    const uint32_t bColSel = (uint32_t)((lane >> 3) & 1) * 8;

#pragma unroll
    for (int s = 0; s < NSTAGE - 1; s++) {
        fill_stage_out(sb + s * OSTAGE_BYTES, A, Bx, rowBase, colBase, s * KC2, tid);
        CP_COMMIT();
    }

    int s_cur = 0, s_nxt = 2;
    for (int c = 0; c < nch; c++) {
        if (c >= nch - 1) CP_WAIT0(); else CP_WAIT1();
        __syncthreads();
        const uint32_t st = sb + s_cur * OSTAGE_BYTES;

        if (c + NSTAGE - 1 < nch) {
            fill_stage_out(sb + s_nxt * OSTAGE_BYTES, A, Bx,
                           rowBase, colBase, (c + NSTAGE - 1) * KC2, tid);
            CP_COMMIT();
        }

#pragma unroll
        for (int kk = 0; kk < KC2; kk += 16) {
            uint32_t bx[2][4];
#pragma unroll
            for (int n2 = 0; n2 < 2; n2++) {
                uint32_t off = (bRowBase + (uint32_t)n2 * 16) * 144 + (kk + bColSel) * 2;
                ldsm4(bx[n2], st + B_OFF + off);
            }
#pragma unroll
            for (int mf = 0; mf < 4; mf++) {
                uint32_t ah[4];
                uint32_t off = aRowOff + (uint32_t)mf * (16 * 144) + (kk + aColSel) * 2;
                ldsm4(ah, st + A_OFF + off);
#pragma unroll
                for (int nf = 0; nf < 4; nf++) {
                    const uint32_t* bp = &bx[nf >> 1][(nf & 1) * 2];
                    mma16816(acc[mf][nf], ah, bp);
                }
            }
        }
        s_cur++; if (s_cur == NSTAGE) s_cur = 0;
        s_nxt++; if (s_nxt == NSTAGE) s_nxt = 0;
    }

    const int rb = rowBase + wr * 64 + (lane >> 2);
    const int cb = colBase + wc * 32 + (lane & 3) * 2;
#pragma unroll
    for (int mf = 0; mf < 4; mf++) {
        const int r = rb + mf * 16;
#pragma unroll
        for (int nf = 0; nf < 4; nf++) {
            const int cc = cb + nf * 8;
            *(float2*)(O + (size_t)r * 1024 + cc) = make_float2(acc[mf][nf][0], acc[mf][nf][1]);
            *(float2*)(O + (size_t)(r + 8) * 1024 + cc) = make_float2(acc[mf][nf][2], acc[mf][nf][3]);
        }
    }
}

// ---------------------------------------------------------------------------
extern "C" void kernel_launch(void* const* d_in, const int* in_sizes, int n_in,
                              void* d_out, int out_size)
{
    const float* x = (const float*)d_in[0];
    const int* xmask = (const int*)d_in[1];
    float* out = (float*)d_out;

    cudaFuncSetAttribute(scores_all,
                         cudaFuncAttributeMaxDynamicSharedMemorySize, SMEM_SC);
    cudaFuncSetAttribute(out_kernel,
                         cudaFuncAttributeMaxDynamicSharedMemorySize, SMEM_OUT);

    mask_scan<<<B_, 256>>>(xmask);

    conv_kernel<<<dim3(32, 32, B_), dim3(32, 8)>>>(x, xmask);

    pad_zero<<<B_, 256>>>();

    scores_all<<<dim3(100, 1, B_), 256, SMEM_SC>>>();

    softmax_kernel<<<B_ * L_, 256>>>();

    out_kernel<<<dim3(8, 4, B_), 512, SMEM_OUT>>>(out);
}

// round 17
// speedup vs baseline: 1.4799x; 1.0366x over previous
#include <cuda_runtime.h>
#include <cuda_fp16.h>
#include <cstdint>

#define B_ 32
#define L_ 1024
#define D_ 1024
typedef __half h16;

// ---------------------------------------------------------------------------
// Scratch (device globals; no allocation in kernel_launch)
// ---------------------------------------------------------------------------
__device__ h16   g_xh  [(size_t)B_ * L_ * D_];  // x hi split (fp16), [b, l, d]
__device__ h16   g_xl  [(size_t)B_ * L_ * D_];  // x lo split
__device__ h16   g_xtc [(size_t)B_ * L_ * D_];  // compact x^T single fp16, [b, d, j]
__device__ float g_scores[(size_t)B_ * L_ * L_]; // compact cols [b, r, j<cnt]
__device__ h16   g_a   [(size_t)B_ * L_ * L_];  // compact alpha (single fp16)
__device__ int   g_idx [B_ * L_];               // valid-row indices (pad 0)
__device__ int   g_idx2[B_ * L_];               // invalid-row indices (pad 0)
__device__ int   g_pos [B_ * L_];               // exclusive prefix of mask
__device__ int   g_cnt [B_];

// ---------------------------------------------------------------------------
// PTX helpers (baseline ISA only — harness targets plain sm_103, no tcgen05)
// ---------------------------------------------------------------------------
__device__ __forceinline__ uint32_t smem_u32(const void* p) {
    uint32_t a;
    asm("{ .reg .u64 t; cvta.to.shared.u64 t, %1; cvt.u32.u64 %0, t; }" : "=r"(a) : "l"(p));
    return a;
}
#define CP_COMMIT() asm volatile("cp.async.commit_group;" ::: "memory")
#define CP_WAIT1()  asm volatile("cp.async.wait_group 1;" ::: "memory")
#define CP_WAIT0()  asm volatile("cp.async.wait_group 0;" ::: "memory")

__device__ __forceinline__ void cp16(uint32_t dst, const void* src) {
    asm volatile("cp.async.cg.shared.global [%0], [%1], 16;" :: "r"(dst), "l"(src));
}
__device__ __forceinline__ void ldsm4(uint32_t* r, uint32_t addr) {
    asm volatile("ldmatrix.sync.aligned.m8n8.x4.shared.b16 {%0,%1,%2,%3}, [%4];"
                 : "=r"(r[0]), "=r"(r[1]), "=r"(r[2]), "=r"(r[3]) : "r"(addr));
}
__device__ __forceinline__ void mma16816(float* c, const uint32_t* a, const uint32_t* b) {
    asm volatile(
        "mma.sync.aligned.m16n8k16.row.col.f32.f16.f16.f32 "
        "{%0,%1,%2,%3}, {%4,%5,%6,%7}, {%8,%9}, {%0,%1,%2,%3};"
        : "+f"(c[0]), "+f"(c[1]), "+f"(c[2]), "+f"(c[3])
        : "r"(a[0]), "r"(a[1]), "r"(a[2]), "r"(a[3]), "r"(b[0]), "r"(b[1]));
}

// ---------------------------------------------------------------------------
// mask_scan: per batch, exclusive prefix -> g_pos, g_idx (valid), g_idx2
// (invalid), g_cnt. ALSO zeroes the compact-transpose pad cols [cnt, cp64)
// (disjoint from everything conv writes, so ordering vs conv is free).
// ---------------------------------------------------------------------------
__global__ __launch_bounds__(256) void mask_scan(const int* __restrict__ xmask)
{
    const int b = blockIdx.x;
    const int tid = threadIdx.x;
    const int lane = tid & 31, wid = tid >> 5;
    const int4 m = *(const int4*)(xmask + b * L_ + tid * 4);
    const int c[4] = { (m.x != 0), (m.y != 0), (m.z != 0), (m.w != 0) };
    const int tot = c[0] + c[1] + c[2] + c[3];

    int incl = tot;
#pragma unroll
    for (int o = 1; o < 32; o <<= 1) {
        int v = __shfl_up_sync(0xffffffffu, incl, o);
        if (lane >= o) incl += v;
    }
    __shared__ int ws[8];
    if (lane == 31) ws[wid] = incl;
    __syncthreads();
    if (tid < 8) {
        int v = ws[tid];
#pragma unroll
        for (int o = 1; o < 8; o <<= 1) {
            int u = __shfl_up_sync(0xffu, v, o);
            if (tid >= o) v += u;
        }
        ws[tid] = v;
    }
    __syncthreads();
    int base = (wid > 0 ? ws[wid - 1] : 0) + (incl - tot);
    const int cnt = ws[7];
    const int cnt2 = L_ - cnt;

    const int l = tid * 4;
    int p = base;
#pragma unroll
    for (int k = 0; k < 4; k++) {
        const int lg = l + k;
        if (c[k]) { g_idx[b * L_ + p] = lg; p++; }
        else      { g_idx2[b * L_ + (lg - p)] = lg; }
    }
    g_pos[b * L_ + l + 0] = base;
    g_pos[b * L_ + l + 1] = base + c[0];
    g_pos[b * L_ + l + 2] = base + c[0] + c[1];
    g_pos[b * L_ + l + 3] = base + c[0] + c[1] + c[2];

    if (tid == 0) g_cnt[b] = cnt;
    for (int j = cnt + tid; j < L_; j += 256) g_idx[b * L_ + j] = 0;
    for (int j = cnt2 + tid; j < L_; j += 256) g_idx2[b * L_ + j] = 0;

    // fused pad_zero: zero xtc pad columns [cnt, cp64)
    const int cp = (cnt + 63) & ~63;
    const int w = cp - cnt;
    if (w > 0) {
        const size_t bo = (size_t)b * L_ * D_;
        for (int t = tid; t < w * 1024; t += 256) {
            int j = cnt + t % w;
            int d = t / w;
            g_xtc[bo + (size_t)d * L_ + j] = __float2half_rn(0.f);
        }
    }
}

// ---------------------------------------------------------------------------
// conv: split x into fp16 hi/lo (row-major; vectorized float4 loads + uint2
// stores), plus COMPACT transposed SINGLE-fp16 copy (for the out GEMM).
// block (32, 8): 32 l-rows x 32 d-cols per block.
// ---------------------------------------------------------------------------
__global__ __launch_bounds__(256) void conv_kernel(const float* __restrict__ x,
                                                   const int* __restrict__ xmask)
{
    __shared__ h16 sh[32][33];
    const int b = blockIdx.z;
    const int d0 = blockIdx.x * 32, l0 = blockIdx.y * 32;
    const int tx = threadIdx.x, ty = threadIdx.y;
    const int t = ty * 32 + tx;
    const float* X = x + (size_t)b * L_ * D_;
    const size_t bo = (size_t)b * L_ * D_;

    {
        const int row = t >> 3;
        const int dc = (t & 7) * 4;
        float4 v = *(const float4*)(X + (size_t)(l0 + row) * D_ + d0 + dc);
        h16 hh[4], ll[4];
        float vv[4] = { v.x, v.y, v.z, v.w };
#pragma unroll
        for (int k = 0; k < 4; k++) {
            hh[k] = __float2half_rn(vv[k]);
            ll[k] = __float2half_rn(vv[k] - __half2float(hh[k]));
            sh[row][dc + k] = hh[k];
        }
        size_t o = bo + (size_t)(l0 + row) * D_ + d0 + dc;
        *(uint2*)(g_xh + o) = *(uint2*)hh;
        *(uint2*)(g_xl + o) = *(uint2*)ll;
    }
    __syncthreads();

    const int l = l0 + tx;
    const int valid = xmask[b * L_ + l];
    const int col = g_pos[b * L_ + l];
    if (valid != 0) {
#pragma unroll
        for (int i = 0; i < 4; i++) {
            int row = ty + i * 8;
            g_xtc[bo + (size_t)(d0 + row) * L_ + col] = sh[tx][row];
        }
    }
}

// ===========================================================================
// Scores GEMM machinery: 128x128 tile, 8 warps, KC=32 2-stage ring, 2 CTA/SM.
// ===========================================================================
#define KC 32
#define TROW 40                         // elements per smem row (80 bytes)
#define TILE_BYTES (128 * TROW * 2)     // 10240
#define STAGE_BYTES (4 * TILE_BYTES)    // 40960: Ah, Al, Bh, Bl
#define SMEM_SC (2 * STAGE_BYTES)       // 81920 >= 128*129*4 transpose stage

__device__ __forceinline__ void fill_tile128_gather(uint32_t dst, const h16* __restrict__ src,
                                                    const int* __restrict__ idxp,
                                                    int base, int k0, int tid)
{
#pragma unroll
    for (int i = 0; i < 2; i++) {
        int idx = i * 256 + tid;
        int row = idx >> 2, seg = idx & 3;
        int gr = idxp[base + row];
        cp16(dst + row * 80 + seg * 16,
             src + (size_t)gr * 1024 + k0 + seg * 8);
    }
}

struct Frag { float acc[4][4][4]; };

__device__ __forceinline__ void gemm_mainloop(
    uint32_t sb, const h16* Ah, const h16* Al,
    const int* idxA, int rowBase, const int* idxB, int colBase,
    int tid, Frag& f)
{
    const int wid = tid >> 5, lane = tid & 31;
    const int wr = wid >> 2, wc = wid & 3;
    const uint32_t aRowOff = (uint32_t)(wr * 64 + (lane & 15)) * 80;
    const uint32_t aColSel = (uint32_t)(lane >> 4) * 8;
    const uint32_t bRowBase = (uint32_t)(wc * 32 + ((lane >> 4) << 3) + (lane & 7));
    const uint32_t bColSel = (uint32_t)((lane >> 3) & 1) * 8;

#pragma unroll
    for (int i = 0; i < 4; i++)
#pragma unroll
        for (int j = 0; j < 4; j++)
#pragma unroll
            for (int k = 0; k < 4; k++) f.acc[i][j][k] = 0.f;

#pragma unroll
    for (int s = 0; s < 2; s++) {
        uint32_t st = sb + s * STAGE_BYTES;
        fill_tile128_gather(st + 0 * TILE_BYTES, Ah, idxA, rowBase, s * KC, tid);
        fill_tile128_gather(st + 1 * TILE_BYTES, Al, idxA, rowBase, s * KC, tid);
        fill_tile128_gather(st + 2 * TILE_BYTES, Ah, idxB, colBase, s * KC, tid);
        fill_tile128_gather(st + 3 * TILE_BYTES, Al, idxB, colBase, s * KC, tid);
        CP_COMMIT();
    }

    for (int c = 0; c < 32; c++) {
        if (c >= 30) CP_WAIT0(); else CP_WAIT1();
        __syncthreads();
        const uint32_t st = sb + (c & 1) * STAGE_BYTES;

#pragma unroll
        for (int kk = 0; kk < KC; kk += 16) {
            uint32_t bh[2][4], bl[2][4];
#pragma unroll
            for (int n2 = 0; n2 < 2; n2++) {
                uint32_t off = (bRowBase + (uint32_t)n2 * 16) * 80 + (kk + bColSel) * 2;
                ldsm4(bh[n2], st + 2 * TILE_BYTES + off);
                ldsm4(bl[n2], st + 3 * TILE_BYTES + off);
            }
#pragma unroll
            for (int mf = 0; mf < 4; mf++) {
                uint32_t ah[4], al[4];
                uint32_t off = aRowOff + (uint32_t)mf * (16 * 80) + (kk + aColSel) * 2;
                ldsm4(ah, st + 0 * TILE_BYTES + off);
                ldsm4(al, st + 1 * TILE_BYTES + off);
#pragma unroll
                for (int nf = 0; nf < 4; nf++) {
                    const uint32_t* bhp = &bh[nf >> 1][(nf & 1) * 2];
                    const uint32_t* blp = &bl[nf >> 1][(nf & 1) * 2];
                    mma16816(f.acc[mf][nf], ah, bhp);
                    mma16816(f.acc[mf][nf], al, bhp);
                    mma16816(f.acc[mf][nf], ah, blp);
                }
            }
        }
        __syncthreads();
        if (c + 2 < 32) {
            const int k0 = (c + 2) * KC;
            fill_tile128_gather(st + 0 * TILE_BYTES, Ah, idxA, rowBase, k0, tid);
            fill_tile128_gather(st + 1 * TILE_BYTES, Al, idxA, rowBase, k0, tid);
            fill_tile128_gather(st + 2 * TILE_BYTES, Ah, idxB, colBase, k0, tid);
            fill_tile128_gather(st + 3 * TILE_BYTES, Al, idxB, colBase, k0, tid);
            CP_COMMIT();
        }
    }
}

// ===========================================================================
// scores_all: ONE launch covering both parts.
//   blockIdx.x <  36 : sym tile (triangular bi>=bj over valid rows), dual write
//   blockIdx.x >= 36 : rect tile (invalid rows x compact cols)
// ===========================================================================
__global__ __launch_bounds__(256, 2) void scores_all()
{
    extern __shared__ char smem[];
    const uint32_t sb = smem_u32(smem);
    float* ss = (float*)smem;
    const int tid = threadIdx.x;
    const int wid = tid >> 5, lane = tid & 31;
    const int wr = wid >> 2, wc = wid & 3;
    const int b = blockIdx.z;
    const int cnt = g_cnt[b];
    const size_t bo = (size_t)b * 1024 * 1024;
    float* O = g_scores + bo;
    const int* idxv = g_idx + b * L_;

    const int rb0 = wr * 64 + (lane >> 2);
    const int cb0 = wc * 32 + (lane & 3) * 2;

    if (blockIdx.x < 36) {
        const int t = blockIdx.x;
        int bi = 0, a0 = 0;
        while (a0 + bi + 1 <= t) { bi++; a0 += bi; }
        const int bj = t - a0;
        const int rowBase = bi * 128;
        const int colBase = bj * 128;
        if (rowBase >= cnt) return;

        Frag f;
        gemm_mainloop(sb, g_xh + bo, g_xl + bo, idxv, rowBase, idxv, colBase, tid, f);

#pragma unroll
        for (int mf = 0; mf < 4; mf++) {
            const int rl = rb0 + mf * 16;
#pragma unroll
            for (int nf = 0; nf < 4; nf++) {
                const int cl = cb0 + nf * 8;
                const int i0 = rowBase + rl, i8 = i0 + 8;
                const int j = colBase + cl;
                if (i0 < cnt) {
                    float v0 = (i0 == j) ? 0.f : f.acc[mf][nf][0];
                    float v1 = (i0 == j + 1) ? 0.f : f.acc[mf][nf][1];
                    *(float2*)(O + (size_t)idxv[i0] * 1024 + j) = make_float2(v0, v1);
                }
                if (i8 < cnt) {
                    float v2 = (i8 == j) ? 0.f : f.acc[mf][nf][2];
                    float v3 = (i8 == j + 1) ? 0.f : f.acc[mf][nf][3];
                    *(float2*)(O + (size_t)idxv[i8] * 1024 + j) = make_float2(v2, v3);
                }
            }
        }

        if (bi == bj) return;

        __syncthreads();
#pragma unroll
        for (int mf = 0; mf < 4; mf++) {
            const int rl = rb0 + mf * 16;
#pragma unroll
            for (int nf = 0; nf < 4; nf++) {
                const int cl = cb0 + nf * 8;
                ss[rl * 129 + cl]           = f.acc[mf][nf][0];
                ss[rl * 129 + cl + 1]       = f.acc[mf][nf][1];
                ss[(rl + 8) * 129 + cl]     = f.acc[mf][nf][2];
                ss[(rl + 8) * 129 + cl + 1] = f.acc[mf][nf][3];
            }
        }
        __syncthreads();
#pragma unroll
        for (int q = 0; q < 16; q++) {
            const int cl = wid * 16 + q;
            const int j = colBase + cl;
            if (j >= cnt) continue;
            const int grow = idxv[j];
            const int rl0 = lane * 4;
            float4 v;
            v.x = ss[(rl0 + 0) * 129 + cl];
            v.y = ss[(rl0 + 1) * 129 + cl];
            v.z = ss[(rl0 + 2) * 129 + cl];
            v.w = ss[(rl0 + 3) * 129 + cl];
            *(float4*)(O + (size_t)grow * 1024 + rowBase + rl0) = v;
        }
    } else {
        const int t = blockIdx.x - 36;
        const int cnt2 = L_ - cnt;
        const int rowBase = (t >> 3) * 128;
        const int colBase = (t & 7) * 128;
        if (rowBase >= cnt2 || colBase >= cnt) return;

        const int* idxi = g_idx2 + b * L_;
        Frag f;
        gemm_mainloop(sb, g_xh + bo, g_xl + bo, idxi, rowBase, idxv, colBase, tid, f);

#pragma unroll
        for (int mf = 0; mf < 4; mf++) {
            const int rl = rb0 + mf * 16;
#pragma unroll
            for (int nf = 0; nf < 4; nf++) {
                const int cl = cb0 + nf * 8;
                const int i0 = rowBase + rl, i8 = i0 + 8;
                const int j = colBase + cl;
                if (i0 < cnt2)
                    *(float2*)(O + (size_t)idxi[i0] * 1024 + j) =
                        make_float2(f.acc[mf][nf][0], f.acc[mf][nf][1]);
                if (i8 < cnt2)
                    *(float2*)(O + (size_t)idxi[i8] * 1024 + j) =
                        make_float2(f.acc[mf][nf][2], f.acc[mf][nf][3]);
            }
        }
    }
}

// ---------------------------------------------------------------------------
// Softmax: TWO rows per 256-thread block (128 threads per row; two
// independent 4-warp reduction groups). Each thread covers up to 8 cols
// (two float4 loads at j and j+512). Writes SINGLE fp16 alpha padded to cp64.
// Row pairs never straddle a batch (1024 | stride).
// ---------------------------------------------------------------------------
__global__ __launch_bounds__(256) void softmax_kernel()
{
    const int tid = threadIdx.x;
    const int g = tid >> 7;             // row group 0/1
    const int tr = tid & 127;
    const int row = blockIdx.x * 2 + g;
    const int b = row >> 10;
    const int cnt = g_cnt[b];
    const int cp = (cnt + 63) & ~63;
    const float* srow = g_scores + (size_t)row * L_;

    const int j0 = tr * 4;
    const int j1 = 512 + tr * 4;

    float s[8];
    int pres[8];
#pragma unroll
    for (int k = 0; k < 4; k++) {
        pres[k] = (j0 + k < cnt);
        pres[4 + k] = (j1 + k < cnt);
    }
    if (j0 + 4 <= cnt) {
        float4 v = *(const float4*)(srow + j0);
        s[0] = v.x; s[1] = v.y; s[2] = v.z; s[3] = v.w;
    } else {
#pragma unroll
        for (int k = 0; k < 4; k++) s[k] = pres[k] ? srow[j0 + k] : 0.f;
    }
    if (j1 + 4 <= cnt) {
        float4 v = *(const float4*)(srow + j1);
        s[4] = v.x; s[5] = v.y; s[6] = v.z; s[7] = v.w;
    } else {
#pragma unroll
        for (int k = 0; k < 4; k++) s[4 + k] = pres[4 + k] ? srow[j1 + k] : 0.f;
    }

    __shared__ float red[8], redm[8];

    // --- max (zeros from diag/masked always participate via 0.f floor) ---
    float mx = 0.f;
#pragma unroll
    for (int k = 0; k < 8; k++) mx = fmaxf(mx, s[k]);
#pragma unroll
    for (int o = 16; o > 0; o >>= 1) mx = fmaxf(mx, __shfl_xor_sync(0xffffffffu, mx, o));
    if ((tid & 31) == 0) red[tid >> 5] = mx;
    __syncthreads();
    mx = fmaxf(fmaxf(red[g * 4 + 0], red[g * 4 + 1]),
               fmaxf(red[g * 4 + 2], red[g * 4 + 3]));

    // --- exp + masked sum ---
    float e[8];
#pragma unroll
    for (int k = 0; k < 8; k++) e[k] = pres[k] ? __expf(s[k] - mx) : 0.f;
    float sm = 0.f;
#pragma unroll
    for (int k = 0; k < 8; k++) sm += e[k];
#pragma unroll
    for (int o = 16; o > 0; o >>= 1) sm += __shfl_xor_sync(0xffffffffu, sm, o);
    if ((tid & 31) == 0) redm[tid >> 5] = sm;
    __syncthreads();
    sm = redm[g * 4 + 0] + redm[g * 4 + 1] + redm[g * 4 + 2] + redm[g * 4 + 3];

    const float denom = sm + 1e-13f * (sm + (float)(L_ - cnt) * __expf(-mx));
    const float inv = 1.f / denom;

    if (j0 < cp) {
        h16 hh[4];
#pragma unroll
        for (int k = 0; k < 4; k++) hh[k] = __float2half_rn(e[k] * inv);
        *(uint2*)(g_a + (size_t)row * L_ + j0) = *(uint2*)hh;
    }
    if (j1 < cp) {
        h16 hh[4];
#pragma unroll
        for (int k = 0; k < 4; k++) hh[k] = __float2half_rn(e[4 + k] * inv);
        *(uint2*)(g_a + (size_t)row * L_ + j1) = *(uint2*)hh;
    }
}

// ===========================================================================
// OUT kernel: 256x128 CTA tile, 512 threads, KC=64 chunks, 3-stage ring,
// runtime K. A = single fp16 alpha; B = single fp16 compact x^T.
// 144B smem rows (144 mod 128 = 16 -> ldmatrix conflict-free).
// ===========================================================================
#define KC2 64
#define NSTAGE 3
#define TROW2 72
#define ATILE2 (256 * TROW2 * 2)        // 36864
#define BTILE2 (128 * TROW2 * 2)        // 18432
#define A_OFF 0
#define B_OFF ATILE2
#define OSTAGE_BYTES (ATILE2 + BTILE2)             // 55296
#define SMEM_OUT (NSTAGE * OSTAGE_BYTES)           // 165888

__device__ __forceinline__ void fill_stage_out(uint32_t st,
                                               const h16* __restrict__ A,
                                               const h16* __restrict__ Bx,
                                               int rowBase, int colBase, int k0, int tid)
{
#pragma unroll
    for (int i = 0; i < 4; i++) {
        int idx = i * 512 + tid;
        int row = idx >> 3, seg = idx & 7;
        cp16(st + A_OFF + row * 144 + seg * 16,
             A + (size_t)(rowBase + row) * 1024 + k0 + seg * 8);
    }
#pragma unroll
    for (int i = 0; i < 2; i++) {
        int idx = i * 512 + tid;
        int row = idx >> 3, seg = idx & 7;
        cp16(st + B_OFF + row * 144 + seg * 16,
             Bx + (size_t)(colBase + row) * 1024 + k0 + seg * 8);
    }
}

__global__ __launch_bounds__(512, 1) void out_kernel(float* __restrict__ gout)
{
    extern __shared__ char smem[];
    const uint32_t sb = smem_u32(smem);
    const int tid = threadIdx.x;
    const int wid = tid >> 5, lane = tid & 31;
    const int wr = wid >> 2, wc = wid & 3;
    const int b = blockIdx.z;
    const int rowBase = blockIdx.y * 256;
    const int colBase = blockIdx.x * 128;
    const int cnt = g_cnt[b];
    const int nch = (cnt + 63) >> 6;

    const size_t bo = (size_t)b * 1024 * 1024;
    const h16* A = g_a + bo;
    const h16* Bx = g_xtc + bo;
    float* O = gout + bo;

    float acc[4][4][4];
#pragma unroll
    for (int i = 0; i < 4; i++)
#pragma unroll
        for (int j = 0; j < 4; j++)
#pragma unroll
            for (int k = 0; k < 4; k++) acc[i][j][k] = 0.f;

    const uint32_t aRowOff = (uint32_t)(wr * 64 + (lane & 15)) * 144;
    const uint32_t aColSel = (uint32_t)(lane >> 4) * 8;
    const uint32_t bRowBase = (uint32_t)(wc * 32 + ((lane >> 4) << 3) + (lane & 7));
    const uint32_t bColSel = (uint32_t)((lane >> 3) & 1) * 8;

#pragma unroll
    for (int s = 0; s < NSTAGE - 1; s++) {
        fill_stage_out(sb + s * OSTAGE_BYTES, A, Bx, rowBase, colBase, s * KC2, tid);
        CP_COMMIT();
    }

    int s_cur = 0, s_nxt = 2;
    for (int c = 0; c < nch; c++) {
        if (c >= nch - 1) CP_WAIT0(); else CP_WAIT1();
        __syncthreads();
        const uint32_t st = sb + s_cur * OSTAGE_BYTES;

        if (c + NSTAGE - 1 < nch) {
            fill_stage_out(sb + s_nxt * OSTAGE_BYTES, A, Bx,
                           rowBase, colBase, (c + NSTAGE - 1) * KC2, tid);
            CP_COMMIT();
        }

#pragma unroll
        for (int kk = 0; kk < KC2; kk += 16) {
            uint32_t bx[2][4];
#pragma unroll
            for (int n2 = 0; n2 < 2; n2++) {
                uint32_t off = (bRowBase + (uint32_t)n2 * 16) * 144 + (kk + bColSel) * 2;
                ldsm4(bx[n2], st + B_OFF + off);
            }
#pragma unroll
            for (int mf = 0; mf < 4; mf++) {
                uint32_t ah[4];
                uint32_t off = aRowOff + (uint32_t)mf * (16 * 144) + (kk + aColSel) * 2;
                ldsm4(ah, st + A_OFF + off);
#pragma unroll
                for (int nf = 0; nf < 4; nf++) {
                    const uint32_t* bp = &bx[nf >> 1][(nf & 1) * 2];
                    mma16816(acc[mf][nf], ah, bp);
                }
            }
        }
        s_cur++; if (s_cur == NSTAGE) s_cur = 0;
        s_nxt++; if (s_nxt == NSTAGE) s_nxt = 0;
    }

    const int rb = rowBase + wr * 64 + (lane >> 2);
    const int cb = colBase + wc * 32 + (lane & 3) * 2;
#pragma unroll
    for (int mf = 0; mf < 4; mf++) {
        const int r = rb + mf * 16;
#pragma unroll
        for (int nf = 0; nf < 4; nf++) {
            const int cc = cb + nf * 8;
            *(float2*)(O + (size_t)r * 1024 + cc) = make_float2(acc[mf][nf][0], acc[mf][nf][1]);
            *(float2*)(O + (size_t)(r + 8) * 1024 + cc) = make_float2(acc[mf][nf][2], acc[mf][nf][3]);
        }
    }
}

// ---------------------------------------------------------------------------
extern "C" void kernel_launch(void* const* d_in, const int* in_sizes, int n_in,
                              void* d_out, int out_size)
{
    const float* x = (const float*)d_in[0];
    const int* xmask = (const int*)d_in[1];
    float* out = (float*)d_out;

    cudaFuncSetAttribute(scores_all,
                         cudaFuncAttributeMaxDynamicSharedMemorySize, SMEM_SC);
    cudaFuncSetAttribute(out_kernel,
                         cudaFuncAttributeMaxDynamicSharedMemorySize, SMEM_OUT);

    mask_scan<<<B_, 256>>>(xmask);

    conv_kernel<<<dim3(32, 32, B_), dim3(32, 8)>>>(x, xmask);

    scores_all<<<dim3(100, 1, B_), 256, SMEM_SC>>>();

    softmax_kernel<<<B_ * L_ / 2, 256>>>();

    out_kernel<<<dim3(8, 4, B_), 512, SMEM_OUT>>>(out);
}